// round 1
// baseline (speedup 1.0000x reference)
#include <cuda_runtime.h>
#include <cuda_bf16.h>
#include <cstdint>

// Problem constants
#define BATCH 4
#define SEQ   2048
#define HID   1024
#define NH    16
#define DK    64
#define MROWS (BATCH*SEQ)          // 8192
#define QKV_N (3*NH*DK)            // 3072

// Scratch (device globals: allocation-free)
__device__ float g_q[(size_t)BATCH*NH*SEQ*DK];     // [B,NH,S,DK]
__device__ float g_k[(size_t)BATCH*NH*SEQ*DK];
__device__ float g_v[(size_t)BATCH*NH*SEQ*DK];
__device__ float g_ctx[(size_t)BATCH*SEQ*NH*DK];   // [B,S,NH*DK]

// ---------------------------------------------------------------------------
// SGEMM: C[M,N] = A[M,K] @ B[K,N] + bias[N]
// BM=BN=128, BK=16, 256 threads, 8x8 per-thread micro-tile.
// mode 0: epilogue scatters into g_q/g_k/g_v (QKV projection)
// mode 1: epilogue writes row-major C (A taken from g_ctx)
// ---------------------------------------------------------------------------
__global__ __launch_bounds__(256, 2)
void sgemm_kernel(const float* __restrict__ A, const float* __restrict__ B,
                  const float* __restrict__ bias, float* __restrict__ C,
                  int N, int K, int mode)
{
    if (mode == 1) A = g_ctx;

    __shared__ float As[16][128];
    __shared__ float Bs[16][128];

    const int tid = threadIdx.x;
    const int tx = tid & 15;
    const int ty = tid >> 4;
    const int rowBase = blockIdx.y * 128;
    const int colBase = blockIdx.x * 128;

    float acc[8][8];
#pragma unroll
    for (int i = 0; i < 8; i++)
#pragma unroll
        for (int j = 0; j < 8; j++) acc[i][j] = 0.f;

    for (int k0 = 0; k0 < K; k0 += 16) {
#pragma unroll
        for (int q = 0; q < 2; q++) {
            int f4 = tid * 2 + q;                    // 0..511
            // A tile: 128 rows x 16 cols -> store transposed As[k][m]
            int ar = f4 >> 2;
            int ac4 = (f4 & 3) << 2;
            float4 av = *(const float4*)&A[(size_t)(rowBase + ar) * K + k0 + ac4];
            As[ac4 + 0][ar] = av.x;
            As[ac4 + 1][ar] = av.y;
            As[ac4 + 2][ar] = av.z;
            As[ac4 + 3][ar] = av.w;
            // B tile: 16 rows x 128 cols
            int bk = f4 >> 5;
            int bn4 = (f4 & 31) << 2;
            *(float4*)&Bs[bk][bn4] =
                *(const float4*)&B[(size_t)(k0 + bk) * N + colBase + bn4];
        }
        __syncthreads();

#pragma unroll
        for (int k = 0; k < 16; k++) {
            float4 a0 = *(const float4*)&As[k][ty * 8];
            float4 a1 = *(const float4*)&As[k][ty * 8 + 4];
            float4 b0 = *(const float4*)&Bs[k][tx * 8];
            float4 b1 = *(const float4*)&Bs[k][tx * 8 + 4];
            float a[8] = {a0.x, a0.y, a0.z, a0.w, a1.x, a1.y, a1.z, a1.w};
            float b[8] = {b0.x, b0.y, b0.z, b0.w, b1.x, b1.y, b1.z, b1.w};
#pragma unroll
            for (int i = 0; i < 8; i++)
#pragma unroll
                for (int j = 0; j < 8; j++)
                    acc[i][j] = fmaf(a[i], b[j], acc[i][j]);
        }
        __syncthreads();
    }

    if (mode == 0) {
        // scatter into q/k/v head-major layout [B,NH,S,DK], fused bias
#pragma unroll
        for (int i = 0; i < 8; i++) {
            int m = rowBase + ty * 8 + i;
            int bb = m >> 11;          // /SEQ
            int ss = m & (SEQ - 1);
#pragma unroll
            for (int j = 0; j < 8; j++) {
                int n = colBase + tx * 8 + j;
                float v = acc[i][j] + bias[n];
                int qkv = n >> 10;     // /(NH*DK)
                int h = (n >> 6) & (NH - 1);
                int d = n & (DK - 1);
                float* dst = (qkv == 0) ? g_q : (qkv == 1) ? g_k : g_v;
                dst[((((size_t)bb * NH) + h) * SEQ + ss) * DK + d] = v;
            }
        }
    } else {
#pragma unroll
        for (int i = 0; i < 8; i++) {
            int m = rowBase + ty * 8 + i;
#pragma unroll
            for (int j = 0; j < 8; j++) {
                int n = colBase + tx * 8 + j;
                C[(size_t)m * N + n] = acc[i][j] + bias[n];
            }
        }
    }
}

// ---------------------------------------------------------------------------
// Flash attention (fp32, online softmax).
// grid = (SEQ/64, BATCH*NH), block = 256. BQ=64 queries, BK=64 keys per tile.
// smem: Qs[64][64], Kt[64][64] (K transposed), Vs[64][64], Ps[64][65],
//       mrow/lrow/crow[64].
// ---------------------------------------------------------------------------
#define SM_QS 0
#define SM_KT 4096
#define SM_VS 8192
#define SM_PS 12288
#define SM_M  (12288 + 64*65)
#define SM_L  (SM_M + 64)
#define SM_C  (SM_L + 64)
#define SM_TOTAL_FLOATS (SM_C + 64)

__global__ __launch_bounds__(256, 2)
void attn_kernel()
{
    extern __shared__ float sm[];
    float* Qs = sm + SM_QS;
    float* Kt = sm + SM_KT;
    float* Vs = sm + SM_VS;
    float* Ps = sm + SM_PS;
    float* mrow = sm + SM_M;
    float* lrow = sm + SM_L;
    float* crow = sm + SM_C;

    const int tid = threadIdx.x;
    const int tx = tid & 15;
    const int ty = tid >> 4;
    const int q0 = blockIdx.x * 64;
    const int bh = blockIdx.y;

    const float* qptr = g_q + ((size_t)bh * SEQ + q0) * DK;
    const float* kbase = g_k + (size_t)bh * SEQ * DK;
    const float* vbase = g_v + (size_t)bh * SEQ * DK;

    // load Q tile (64x64 = 1024 float4)
#pragma unroll
    for (int it = 0; it < 4; it++) {
        int i = tid + it * 256;
        ((float4*)Qs)[i] = ((const float4*)qptr)[i];
    }
    if (tid < 64) { mrow[tid] = -1e30f; lrow[tid] = 0.f; }

    float acc_o[4][4];
#pragma unroll
    for (int i = 0; i < 4; i++)
#pragma unroll
        for (int j = 0; j < 4; j++) acc_o[i][j] = 0.f;

    for (int kt = 0; kt < SEQ / 64; kt++) {
        const float* kptr = kbase + (size_t)kt * 64 * DK;
        const float* vptr = vbase + (size_t)kt * 64 * DK;

        __syncthreads();   // prior iter done reading Kt/Vs/Ps (no-op 1st iter; also covers Qs init)
#pragma unroll
        for (int it = 0; it < 4; it++) {
            int i = tid + it * 256;
            float4 kv = ((const float4*)kptr)[i];
            int c = i >> 4;            // seq index within tile
            int kk = (i & 15) << 2;    // dim base
            Kt[(kk + 0) * 64 + c] = kv.x;
            Kt[(kk + 1) * 64 + c] = kv.y;
            Kt[(kk + 2) * 64 + c] = kv.z;
            Kt[(kk + 3) * 64 + c] = kv.w;
            ((float4*)Vs)[i] = ((const float4*)vptr)[i];
        }
        __syncthreads();

        // S = Q @ K^T  (4x4 micro-tile per thread)
        float s_acc[4][4];
#pragma unroll
        for (int i = 0; i < 4; i++)
#pragma unroll
            for (int j = 0; j < 4; j++) s_acc[i][j] = 0.f;

#pragma unroll
        for (int k = 0; k < 64; k++) {
            float a0 = Qs[(ty * 4 + 0) * 64 + k];
            float a1 = Qs[(ty * 4 + 1) * 64 + k];
            float a2 = Qs[(ty * 4 + 2) * 64 + k];
            float a3 = Qs[(ty * 4 + 3) * 64 + k];
            float4 b = *(const float4*)&Kt[k * 64 + tx * 4];
            s_acc[0][0] = fmaf(a0, b.x, s_acc[0][0]);
            s_acc[0][1] = fmaf(a0, b.y, s_acc[0][1]);
            s_acc[0][2] = fmaf(a0, b.z, s_acc[0][2]);
            s_acc[0][3] = fmaf(a0, b.w, s_acc[0][3]);
            s_acc[1][0] = fmaf(a1, b.x, s_acc[1][0]);
            s_acc[1][1] = fmaf(a1, b.y, s_acc[1][1]);
            s_acc[1][2] = fmaf(a1, b.z, s_acc[1][2]);
            s_acc[1][3] = fmaf(a1, b.w, s_acc[1][3]);
            s_acc[2][0] = fmaf(a2, b.x, s_acc[2][0]);
            s_acc[2][1] = fmaf(a2, b.y, s_acc[2][1]);
            s_acc[2][2] = fmaf(a2, b.z, s_acc[2][2]);
            s_acc[2][3] = fmaf(a2, b.w, s_acc[2][3]);
            s_acc[3][0] = fmaf(a3, b.x, s_acc[3][0]);
            s_acc[3][1] = fmaf(a3, b.y, s_acc[3][1]);
            s_acc[3][2] = fmaf(a3, b.z, s_acc[3][2]);
            s_acc[3][3] = fmaf(a3, b.w, s_acc[3][3]);
        }
        const float scale = 0.125f;  // 1/sqrt(64)
#pragma unroll
        for (int i = 0; i < 4; i++)
#pragma unroll
            for (int j = 0; j < 4; j++)
                Ps[(ty * 4 + i) * 65 + tx * 4 + j] = s_acc[i][j] * scale;
        __syncthreads();

        // online softmax (row-wise, 64 threads)
        if (tid < 64) {
            float mo = mrow[tid];
            float mx = mo;
#pragma unroll 8
            for (int c = 0; c < 64; c++) mx = fmaxf(mx, Ps[tid * 65 + c]);
            float corr = __expf(mo - mx);
            float ls = 0.f;
#pragma unroll 8
            for (int c = 0; c < 64; c++) {
                float p = __expf(Ps[tid * 65 + c] - mx);
                Ps[tid * 65 + c] = p;
                ls += p;
            }
            mrow[tid] = mx;
            lrow[tid] = lrow[tid] * corr + ls;
            crow[tid] = corr;
        }
        __syncthreads();

        // O = O*corr + P @ V
        float cr[4];
#pragma unroll
        for (int i = 0; i < 4; i++) cr[i] = crow[ty * 4 + i];
#pragma unroll
        for (int i = 0; i < 4; i++)
#pragma unroll
            for (int j = 0; j < 4; j++) acc_o[i][j] *= cr[i];

#pragma unroll
        for (int k = 0; k < 64; k++) {
            float a0 = Ps[(ty * 4 + 0) * 65 + k];
            float a1 = Ps[(ty * 4 + 1) * 65 + k];
            float a2 = Ps[(ty * 4 + 2) * 65 + k];
            float a3 = Ps[(ty * 4 + 3) * 65 + k];
            float4 b = *(const float4*)&Vs[k * 64 + tx * 4];
            acc_o[0][0] = fmaf(a0, b.x, acc_o[0][0]);
            acc_o[0][1] = fmaf(a0, b.y, acc_o[0][1]);
            acc_o[0][2] = fmaf(a0, b.z, acc_o[0][2]);
            acc_o[0][3] = fmaf(a0, b.w, acc_o[0][3]);
            acc_o[1][0] = fmaf(a1, b.x, acc_o[1][0]);
            acc_o[1][1] = fmaf(a1, b.y, acc_o[1][1]);
            acc_o[1][2] = fmaf(a1, b.z, acc_o[1][2]);
            acc_o[1][3] = fmaf(a1, b.w, acc_o[1][3]);
            acc_o[2][0] = fmaf(a2, b.x, acc_o[2][0]);
            acc_o[2][1] = fmaf(a2, b.y, acc_o[2][1]);
            acc_o[2][2] = fmaf(a2, b.z, acc_o[2][2]);
            acc_o[2][3] = fmaf(a2, b.w, acc_o[2][3]);
            acc_o[3][0] = fmaf(a3, b.x, acc_o[3][0]);
            acc_o[3][1] = fmaf(a3, b.y, acc_o[3][1]);
            acc_o[3][2] = fmaf(a3, b.z, acc_o[3][2]);
            acc_o[3][3] = fmaf(a3, b.w, acc_o[3][3]);
        }
    }

    // epilogue: ctx[B,S,NH*DK]
    int bb = bh >> 4;
    int h = bh & (NH - 1);
#pragma unroll
    for (int i = 0; i < 4; i++) {
        float inv = 1.f / lrow[ty * 4 + i];
        size_t row = (size_t)(bb * SEQ + q0 + ty * 4 + i) * (NH * DK) + h * DK;
#pragma unroll
        for (int j = 0; j < 4; j++)
            g_ctx[row + tx * 4 + j] = acc_o[i][j] * inv;
    }
}

// ---------------------------------------------------------------------------
extern "C" void kernel_launch(void* const* d_in, const int* in_sizes, int n_in,
                              void* d_out, int out_size)
{
    const float* x  = (const float*)d_in[0];
    const float* W1 = (const float*)d_in[1];
    const float* b1 = (const float*)d_in[2];
    const float* W2 = (const float*)d_in[3];
    const float* b2 = (const float*)d_in[4];
    float* out = (float*)d_out;

    // 1) QKV projection: [8192,1024] @ [1024,3072] + b1 -> q/k/v scratch
    dim3 g1(QKV_N / 128, MROWS / 128);
    sgemm_kernel<<<g1, 256>>>(x, W1, b1, nullptr, QKV_N, HID, 0);

    // 2) flash attention -> g_ctx
    size_t smem_bytes = (size_t)SM_TOTAL_FLOATS * sizeof(float);
    cudaFuncSetAttribute(attn_kernel,
                         cudaFuncAttributeMaxDynamicSharedMemorySize,
                         (int)smem_bytes);
    attn_kernel<<<dim3(SEQ / 64, BATCH * NH), 256, smem_bytes>>>();

    // 3) output projection: g_ctx @ W2 + b2 -> out
    dim3 g3(HID / 128, MROWS / 128);
    sgemm_kernel<<<g3, 256>>>(nullptr, W2, b2, out, HID, HID, 1);
}

// round 3
// speedup vs baseline: 1.3890x; 1.3890x over previous
#include <cuda_runtime.h>
#include <cuda_bf16.h>
#include <cstdint>

// Problem constants
#define BATCH 4
#define SEQ   2048
#define HID   1024
#define NH    16
#define DK    64
#define MROWS (BATCH*SEQ)          // 8192
#define QKV_N (3*NH*DK)            // 3072

// Scratch (device globals: allocation-free)
__device__ float g_q[(size_t)BATCH*NH*SEQ*DK];     // [B,NH,S,DK]
__device__ float g_k[(size_t)BATCH*NH*SEQ*DK];
__device__ float g_v[(size_t)BATCH*NH*SEQ*DK];
__device__ float g_ctx[(size_t)BATCH*SEQ*NH*DK];   // [B,S,NH*DK]

__device__ __forceinline__ uint32_t f2tf(float x) {
    uint32_t u; asm("cvt.rna.tf32.f32 %0, %1;" : "=r"(u) : "f"(x)); return u;
}

// ---------------------------------------------------------------------------
// tf32 mma.sync GEMM: C[M,N] = A[M,K] @ B[K,N] + bias[N]
// BM=BN=128, BK=32, 256 threads (8 warps: 2(M) x 4(N), each 64x32 warp tile).
// m16n8k8 fragments, register accumulators, cvt.rna tf32 rounding on STS.
// mode 0: epilogue scatters into g_q/g_k/g_v.  mode 1: row-major C (A=g_ctx).
// ---------------------------------------------------------------------------
__global__ __launch_bounds__(256)
void mma_gemm(const float* __restrict__ A_in, const float* __restrict__ B,
              const float* __restrict__ bias, float* __restrict__ C,
              int N, int K, int mode)
{
    __shared__ uint32_t As[128][36];   // [m][k], stride 36: frag bank = 4r+c (bijective)
    __shared__ uint32_t Bs[32][136];   // [k][n], stride 136: frag bank = 8c+r (bijective)

    const float* A = (mode == 1) ? g_ctx : A_in;

    const int tid = threadIdx.x;
    const int lane = tid & 31;
    const int wid = tid >> 5;
    const int wm = (wid & 1) * 64;     // warp M offset
    const int wn = (wid >> 1) * 32;    // warp N offset
    const int gr = lane >> 2;          // fragment group row 0..7
    const int lc = lane & 3;           // fragment k sub-col 0..3
    const int rowBase = blockIdx.y * 128;
    const int colBase = blockIdx.x * 128;

    float acc[4][4][4];
#pragma unroll
    for (int i = 0; i < 4; i++)
#pragma unroll
        for (int j = 0; j < 4; j++)
#pragma unroll
            for (int r = 0; r < 4; r++) acc[i][j][r] = 0.f;

    // global-load addressing
    const int a_r = tid >> 3;            // 0..31 (+32 per it)
    const int a_c = (tid & 7) * 4;       // k col base
    const int b_r = tid >> 5;            // 0..7 (+8 per it)
    const int b_c = (tid & 31) * 4;      // n col base

    float4 pa[4], pb[4];
#pragma unroll
    for (int it = 0; it < 4; it++) {
        pa[it] = *(const float4*)&A[(size_t)(rowBase + a_r + it * 32) * K + a_c];
        pb[it] = *(const float4*)&B[(size_t)(b_r + it * 8) * N + colBase + b_c];
    }

    const int KT = K / 32;
    for (int kt = 0; kt < KT; kt++) {
#pragma unroll
        for (int it = 0; it < 4; it++) {
            uint4 va = { f2tf(pa[it].x), f2tf(pa[it].y), f2tf(pa[it].z), f2tf(pa[it].w) };
            *(uint4*)&As[a_r + it * 32][a_c] = va;
            uint4 vb = { f2tf(pb[it].x), f2tf(pb[it].y), f2tf(pb[it].z), f2tf(pb[it].w) };
            *(uint4*)&Bs[b_r + it * 8][b_c] = vb;
        }
        __syncthreads();

        if (kt + 1 < KT) {
            int k0 = (kt + 1) * 32;
#pragma unroll
            for (int it = 0; it < 4; it++) {
                pa[it] = *(const float4*)&A[(size_t)(rowBase + a_r + it * 32) * K + k0 + a_c];
                pb[it] = *(const float4*)&B[(size_t)(k0 + b_r + it * 8) * N + colBase + b_c];
            }
        }

#pragma unroll
        for (int kk = 0; kk < 32; kk += 8) {
            uint32_t af[4][4], bf[4][2];
#pragma unroll
            for (int mf = 0; mf < 4; mf++) {
                int m = wm + mf * 16 + gr;
                af[mf][0] = As[m][kk + lc];
                af[mf][1] = As[m + 8][kk + lc];
                af[mf][2] = As[m][kk + lc + 4];
                af[mf][3] = As[m + 8][kk + lc + 4];
            }
#pragma unroll
            for (int nf = 0; nf < 4; nf++) {
                int n = wn + nf * 8 + gr;
                bf[nf][0] = Bs[kk + lc][n];
                bf[nf][1] = Bs[kk + lc + 4][n];
            }
#pragma unroll
            for (int mf = 0; mf < 4; mf++)
#pragma unroll
                for (int nf = 0; nf < 4; nf++) {
                    asm volatile(
                        "mma.sync.aligned.m16n8k8.row.col.f32.tf32.tf32.f32 "
                        "{%0,%1,%2,%3}, {%4,%5,%6,%7}, {%8,%9}, {%0,%1,%2,%3};"
                        : "+f"(acc[mf][nf][0]), "+f"(acc[mf][nf][1]),
                          "+f"(acc[mf][nf][2]), "+f"(acc[mf][nf][3])
                        : "r"(af[mf][0]), "r"(af[mf][1]), "r"(af[mf][2]), "r"(af[mf][3]),
                          "r"(bf[nf][0]), "r"(bf[nf][1]));
                }
        }
        __syncthreads();
    }

    // epilogue: c0,c1 at (m, n0), (m, n0+1); c2,c3 at (m+8, ...)
#pragma unroll
    for (int mf = 0; mf < 4; mf++) {
#pragma unroll
        for (int nf = 0; nf < 4; nf++) {
            int m0 = rowBase + wm + mf * 16 + gr;
            int n0 = colBase + wn + nf * 8 + lc * 2;
            float bi0 = bias[n0], bi1 = bias[n0 + 1];
#pragma unroll
            for (int half = 0; half < 2; half++) {
                int m = m0 + half * 8;
                float v0 = acc[mf][nf][half * 2 + 0] + bi0;
                float v1 = acc[mf][nf][half * 2 + 1] + bi1;
                if (mode == 0) {
                    int bb = m >> 11, ss = m & (SEQ - 1);
                    int qkv = n0 >> 10;
                    int h = (n0 >> 6) & (NH - 1);
                    int d = n0 & (DK - 1);
                    float* dst = (qkv == 0) ? g_q : (qkv == 1) ? g_k : g_v;
                    float* p = dst + ((((size_t)bb * NH) + h) * SEQ + ss) * DK + d;
                    p[0] = v0; p[1] = v1;
                } else {
                    float* p = C + (size_t)m * N + n0;
                    p[0] = v0; p[1] = v1;
                }
            }
        }
    }
}

// ---------------------------------------------------------------------------
// Flash attention (fp32, online softmax) — unchanged known-good kernel.
// ---------------------------------------------------------------------------
#define SM_QS 0
#define SM_KT 4096
#define SM_VS 8192
#define SM_PS 12288
#define SM_M  (12288 + 64*65)
#define SM_L  (SM_M + 64)
#define SM_C  (SM_L + 64)
#define SM_TOTAL_FLOATS (SM_C + 64)

__global__ __launch_bounds__(256, 2)
void attn_kernel()
{
    extern __shared__ float sm[];
    float* Qs = sm + SM_QS;
    float* Kt = sm + SM_KT;
    float* Vs = sm + SM_VS;
    float* Ps = sm + SM_PS;
    float* mrow = sm + SM_M;
    float* lrow = sm + SM_L;
    float* crow = sm + SM_C;

    const int tid = threadIdx.x;
    const int tx = tid & 15;
    const int ty = tid >> 4;
    const int q0 = blockIdx.x * 64;
    const int bh = blockIdx.y;

    const float* qptr = g_q + ((size_t)bh * SEQ + q0) * DK;
    const float* kbase = g_k + (size_t)bh * SEQ * DK;
    const float* vbase = g_v + (size_t)bh * SEQ * DK;

#pragma unroll
    for (int it = 0; it < 4; it++) {
        int i = tid + it * 256;
        ((float4*)Qs)[i] = ((const float4*)qptr)[i];
    }
    if (tid < 64) { mrow[tid] = -1e30f; lrow[tid] = 0.f; }

    float acc_o[4][4];
#pragma unroll
    for (int i = 0; i < 4; i++)
#pragma unroll
        for (int j = 0; j < 4; j++) acc_o[i][j] = 0.f;

    for (int kt = 0; kt < SEQ / 64; kt++) {
        const float* kptr = kbase + (size_t)kt * 64 * DK;
        const float* vptr = vbase + (size_t)kt * 64 * DK;

        __syncthreads();
#pragma unroll
        for (int it = 0; it < 4; it++) {
            int i = tid + it * 256;
            float4 kv = ((const float4*)kptr)[i];
            int c = i >> 4;
            int kk = (i & 15) << 2;
            Kt[(kk + 0) * 64 + c] = kv.x;
            Kt[(kk + 1) * 64 + c] = kv.y;
            Kt[(kk + 2) * 64 + c] = kv.z;
            Kt[(kk + 3) * 64 + c] = kv.w;
            ((float4*)Vs)[i] = ((const float4*)vptr)[i];
        }
        __syncthreads();

        float s_acc[4][4];
#pragma unroll
        for (int i = 0; i < 4; i++)
#pragma unroll
            for (int j = 0; j < 4; j++) s_acc[i][j] = 0.f;

#pragma unroll
        for (int k = 0; k < 64; k++) {
            float a0 = Qs[(ty * 4 + 0) * 64 + k];
            float a1 = Qs[(ty * 4 + 1) * 64 + k];
            float a2 = Qs[(ty * 4 + 2) * 64 + k];
            float a3 = Qs[(ty * 4 + 3) * 64 + k];
            float4 b = *(const float4*)&Kt[k * 64 + tx * 4];
            s_acc[0][0] = fmaf(a0, b.x, s_acc[0][0]);
            s_acc[0][1] = fmaf(a0, b.y, s_acc[0][1]);
            s_acc[0][2] = fmaf(a0, b.z, s_acc[0][2]);
            s_acc[0][3] = fmaf(a0, b.w, s_acc[0][3]);
            s_acc[1][0] = fmaf(a1, b.x, s_acc[1][0]);
            s_acc[1][1] = fmaf(a1, b.y, s_acc[1][1]);
            s_acc[1][2] = fmaf(a1, b.z, s_acc[1][2]);
            s_acc[1][3] = fmaf(a1, b.w, s_acc[1][3]);
            s_acc[2][0] = fmaf(a2, b.x, s_acc[2][0]);
            s_acc[2][1] = fmaf(a2, b.y, s_acc[2][1]);
            s_acc[2][2] = fmaf(a2, b.z, s_acc[2][2]);
            s_acc[2][3] = fmaf(a2, b.w, s_acc[2][3]);
            s_acc[3][0] = fmaf(a3, b.x, s_acc[3][0]);
            s_acc[3][1] = fmaf(a3, b.y, s_acc[3][1]);
            s_acc[3][2] = fmaf(a3, b.z, s_acc[3][2]);
            s_acc[3][3] = fmaf(a3, b.w, s_acc[3][3]);
        }
        const float scale = 0.125f;
#pragma unroll
        for (int i = 0; i < 4; i++)
#pragma unroll
            for (int j = 0; j < 4; j++)
                Ps[(ty * 4 + i) * 65 + tx * 4 + j] = s_acc[i][j] * scale;
        __syncthreads();

        if (tid < 64) {
            float mo = mrow[tid];
            float mx = mo;
#pragma unroll 8
            for (int c = 0; c < 64; c++) mx = fmaxf(mx, Ps[tid * 65 + c]);
            float corr = __expf(mo - mx);
            float ls = 0.f;
#pragma unroll 8
            for (int c = 0; c < 64; c++) {
                float p = __expf(Ps[tid * 65 + c] - mx);
                Ps[tid * 65 + c] = p;
                ls += p;
            }
            mrow[tid] = mx;
            lrow[tid] = lrow[tid] * corr + ls;
            crow[tid] = corr;
        }
        __syncthreads();

        float cr[4];
#pragma unroll
        for (int i = 0; i < 4; i++) cr[i] = crow[ty * 4 + i];
#pragma unroll
        for (int i = 0; i < 4; i++)
#pragma unroll
            for (int j = 0; j < 4; j++) acc_o[i][j] *= cr[i];

#pragma unroll
        for (int k = 0; k < 64; k++) {
            float a0 = Ps[(ty * 4 + 0) * 65 + k];
            float a1 = Ps[(ty * 4 + 1) * 65 + k];
            float a2 = Ps[(ty * 4 + 2) * 65 + k];
            float a3 = Ps[(ty * 4 + 3) * 65 + k];
            float4 b = *(const float4*)&Vs[k * 64 + tx * 4];
            acc_o[0][0] = fmaf(a0, b.x, acc_o[0][0]);
            acc_o[0][1] = fmaf(a0, b.y, acc_o[0][1]);
            acc_o[0][2] = fmaf(a0, b.z, acc_o[0][2]);
            acc_o[0][3] = fmaf(a0, b.w, acc_o[0][3]);
            acc_o[1][0] = fmaf(a1, b.x, acc_o[1][0]);
            acc_o[1][1] = fmaf(a1, b.y, acc_o[1][1]);
            acc_o[1][2] = fmaf(a1, b.z, acc_o[1][2]);
            acc_o[1][3] = fmaf(a1, b.w, acc_o[1][3]);
            acc_o[2][0] = fmaf(a2, b.x, acc_o[2][0]);
            acc_o[2][1] = fmaf(a2, b.y, acc_o[2][1]);
            acc_o[2][2] = fmaf(a2, b.z, acc_o[2][2]);
            acc_o[2][3] = fmaf(a2, b.w, acc_o[2][3]);
            acc_o[3][0] = fmaf(a3, b.x, acc_o[3][0]);
            acc_o[3][1] = fmaf(a3, b.y, acc_o[3][1]);
            acc_o[3][2] = fmaf(a3, b.z, acc_o[3][2]);
            acc_o[3][3] = fmaf(a3, b.w, acc_o[3][3]);
        }
    }

    int bb = bh >> 4;
    int h = bh & (NH - 1);
#pragma unroll
    for (int i = 0; i < 4; i++) {
        float inv = 1.f / lrow[ty * 4 + i];
        size_t row = (size_t)(bb * SEQ + q0 + ty * 4 + i) * (NH * DK) + h * DK;
#pragma unroll
        for (int j = 0; j < 4; j++)
            g_ctx[row + tx * 4 + j] = acc_o[i][j] * inv;
    }
}

// ---------------------------------------------------------------------------
extern "C" void kernel_launch(void* const* d_in, const int* in_sizes, int n_in,
                              void* d_out, int out_size)
{
    const float* x  = (const float*)d_in[0];
    const float* W1 = (const float*)d_in[1];
    const float* b1 = (const float*)d_in[2];
    const float* W2 = (const float*)d_in[3];
    const float* b2 = (const float*)d_in[4];
    float* out = (float*)d_out;

    // 1) QKV projection (tf32 mma.sync): x @ W1 + b1 -> q/k/v scratch
    mma_gemm<<<dim3(QKV_N / 128, MROWS / 128), 256>>>(x, W1, b1, nullptr,
                                                      QKV_N, HID, 0);

    // 2) flash attention -> g_ctx
    size_t smem_bytes = (size_t)SM_TOTAL_FLOATS * sizeof(float);
    cudaFuncSetAttribute(attn_kernel,
                         cudaFuncAttributeMaxDynamicSharedMemorySize,
                         (int)smem_bytes);
    attn_kernel<<<dim3(SEQ / 64, BATCH * NH), 256, smem_bytes>>>();

    // 3) output projection (tf32 mma.sync): g_ctx @ W2 + b2 -> out
    mma_gemm<<<dim3(HID / 128, MROWS / 128), 256>>>(nullptr, W2, b2, out,
                                                    HID, HID, 1);
}

// round 4
// speedup vs baseline: 3.5983x; 2.5905x over previous
#include <cuda_runtime.h>
#include <cuda_bf16.h>
#include <cstdint>

// Problem constants
#define BATCH 4
#define SEQ   2048
#define HID   1024
#define NH    16
#define DK    64
#define MROWS (BATCH*SEQ)          // 8192
#define QKV_N (3*NH*DK)            // 3072

// Scratch (device globals: allocation-free)
__device__ float g_q[(size_t)BATCH*NH*SEQ*DK];     // [B,NH,S,DK]
__device__ float g_k[(size_t)BATCH*NH*SEQ*DK];
__device__ float g_v[(size_t)BATCH*NH*SEQ*DK];
__device__ float g_ctx[(size_t)BATCH*SEQ*NH*DK];   // [B,S,NH*DK]

__device__ __forceinline__ uint32_t f2tf(float x) {
    uint32_t u; asm("cvt.rna.tf32.f32 %0, %1;" : "=r"(u) : "f"(x)); return u;
}

#define MMA_TF32(d, a0,a1,a2,a3, b0,b1) \
    asm volatile( \
        "mma.sync.aligned.m16n8k8.row.col.f32.tf32.tf32.f32 " \
        "{%0,%1,%2,%3}, {%4,%5,%6,%7}, {%8,%9}, {%0,%1,%2,%3};" \
        : "+f"((d)[0]), "+f"((d)[1]), "+f"((d)[2]), "+f"((d)[3]) \
        : "r"(a0), "r"(a1), "r"(a2), "r"(a3), "r"(b0), "r"(b1))

// ---------------------------------------------------------------------------
// tf32 mma.sync GEMM: C[M,N] = A[M,K] @ B[K,N] + bias[N]   (unchanged, passing)
// ---------------------------------------------------------------------------
__global__ __launch_bounds__(256)
void mma_gemm(const float* __restrict__ A_in, const float* __restrict__ B,
              const float* __restrict__ bias, float* __restrict__ C,
              int N, int K, int mode)
{
    __shared__ uint32_t As[128][36];
    __shared__ uint32_t Bs[32][136];

    const float* A = (mode == 1) ? g_ctx : A_in;

    const int tid = threadIdx.x;
    const int lane = tid & 31;
    const int wid = tid >> 5;
    const int wm = (wid & 1) * 64;
    const int wn = (wid >> 1) * 32;
    const int gr = lane >> 2;
    const int lc = lane & 3;
    const int rowBase = blockIdx.y * 128;
    const int colBase = blockIdx.x * 128;

    float acc[4][4][4];
#pragma unroll
    for (int i = 0; i < 4; i++)
#pragma unroll
        for (int j = 0; j < 4; j++)
#pragma unroll
            for (int r = 0; r < 4; r++) acc[i][j][r] = 0.f;

    const int a_r = tid >> 3;
    const int a_c = (tid & 7) * 4;
    const int b_r = tid >> 5;
    const int b_c = (tid & 31) * 4;

    float4 pa[4], pb[4];
#pragma unroll
    for (int it = 0; it < 4; it++) {
        pa[it] = *(const float4*)&A[(size_t)(rowBase + a_r + it * 32) * K + a_c];
        pb[it] = *(const float4*)&B[(size_t)(b_r + it * 8) * N + colBase + b_c];
    }

    const int KT = K / 32;
    for (int kt = 0; kt < KT; kt++) {
#pragma unroll
        for (int it = 0; it < 4; it++) {
            uint4 va = { f2tf(pa[it].x), f2tf(pa[it].y), f2tf(pa[it].z), f2tf(pa[it].w) };
            *(uint4*)&As[a_r + it * 32][a_c] = va;
            uint4 vb = { f2tf(pb[it].x), f2tf(pb[it].y), f2tf(pb[it].z), f2tf(pb[it].w) };
            *(uint4*)&Bs[b_r + it * 8][b_c] = vb;
        }
        __syncthreads();

        if (kt + 1 < KT) {
            int k0 = (kt + 1) * 32;
#pragma unroll
            for (int it = 0; it < 4; it++) {
                pa[it] = *(const float4*)&A[(size_t)(rowBase + a_r + it * 32) * K + k0 + a_c];
                pb[it] = *(const float4*)&B[(size_t)(k0 + b_r + it * 8) * N + colBase + b_c];
            }
        }

#pragma unroll
        for (int kk = 0; kk < 32; kk += 8) {
            uint32_t af[4][4], bf[4][2];
#pragma unroll
            for (int mf = 0; mf < 4; mf++) {
                int m = wm + mf * 16 + gr;
                af[mf][0] = As[m][kk + lc];
                af[mf][1] = As[m + 8][kk + lc];
                af[mf][2] = As[m][kk + lc + 4];
                af[mf][3] = As[m + 8][kk + lc + 4];
            }
#pragma unroll
            for (int nf = 0; nf < 4; nf++) {
                int n = wn + nf * 8 + gr;
                bf[nf][0] = Bs[kk + lc][n];
                bf[nf][1] = Bs[kk + lc + 4][n];
            }
#pragma unroll
            for (int mf = 0; mf < 4; mf++)
#pragma unroll
                for (int nf = 0; nf < 4; nf++)
                    MMA_TF32(acc[mf][nf], af[mf][0], af[mf][1], af[mf][2], af[mf][3],
                             bf[nf][0], bf[nf][1]);
        }
        __syncthreads();
    }

#pragma unroll
    for (int mf = 0; mf < 4; mf++) {
#pragma unroll
        for (int nf = 0; nf < 4; nf++) {
            int m0 = rowBase + wm + mf * 16 + gr;
            int n0 = colBase + wn + nf * 8 + lc * 2;
            float bi0 = bias[n0], bi1 = bias[n0 + 1];
#pragma unroll
            for (int half = 0; half < 2; half++) {
                int m = m0 + half * 8;
                float v0 = acc[mf][nf][half * 2 + 0] + bi0;
                float v1 = acc[mf][nf][half * 2 + 1] + bi1;
                if (mode == 0) {
                    int bb = m >> 11, ss = m & (SEQ - 1);
                    int qkv = n0 >> 10;
                    int h = (n0 >> 6) & (NH - 1);
                    int d = n0 & (DK - 1);
                    float* dst = (qkv == 0) ? g_q : (qkv == 1) ? g_k : g_v;
                    float* p = dst + ((((size_t)bb * NH) + h) * SEQ + ss) * DK + d;
                    p[0] = v0; p[1] = v1;
                } else {
                    float* p = C + (size_t)m * N + n0;
                    p[0] = v0; p[1] = v1;
                }
            }
        }
    }
}

// ---------------------------------------------------------------------------
// Tensor-core flash attention (tf32 mma.sync, online softmax in registers).
// 128 threads = 4 warps; warp owns 32 q-rows (2 m-frags), full N=64.
// BQ=128, BK=64, 32 k-tiles. Q pre-scaled+tf32 in smem; K/V tf32 in smem.
// Smem strides: Q/K 68 (bank 4r+c bijective), V 72 (bank 8r+c bijective).
// ---------------------------------------------------------------------------
#define QS_STR 68
#define VS_STR 72
#define SM_Q   0
#define SM_K   (128*QS_STR)            // 8704
#define SM_V   (SM_K + 64*QS_STR)      // 13056
#define ATTN_SMEM_WORDS (SM_V + 64*VS_STR)   // 17664 words = 70656 B

__global__ __launch_bounds__(128, 2)
void attn_mma()
{
    extern __shared__ uint32_t smw[];
    uint32_t* Qs = smw + SM_Q;
    uint32_t* Ks = smw + SM_K;
    uint32_t* Vs = smw + SM_V;

    const int tid = threadIdx.x;
    const int lane = tid & 31;
    const int wid = tid >> 5;
    const int gr = lane >> 2;
    const int lc = lane & 3;
    const int q0 = blockIdx.x * 128;
    const int bh = blockIdx.y;
    const int wrow = wid * 32;

    const float* qg = g_q + ((size_t)bh * SEQ + q0) * DK;
    const float* kbase = g_k + (size_t)bh * SEQ * DK;
    const float* vbase = g_v + (size_t)bh * SEQ * DK;

    // Load Q tile: 128x64, scale by 1/8 (exact), cvt to tf32
#pragma unroll
    for (int it = 0; it < 16; it++) {
        int i = tid + it * 128;              // float4 index, 2048 total
        int r = i >> 4, c4 = (i & 15) << 2;
        float4 v = *(const float4*)&qg[(size_t)r * DK + c4];
        uint4 u = { f2tf(v.x * 0.125f), f2tf(v.y * 0.125f),
                    f2tf(v.z * 0.125f), f2tf(v.w * 0.125f) };
        *(uint4*)&Qs[r * QS_STR + c4] = u;
    }

    float o[2][8][4];
#pragma unroll
    for (int mf = 0; mf < 2; mf++)
#pragma unroll
        for (int nf = 0; nf < 8; nf++)
#pragma unroll
            for (int r = 0; r < 4; r++) o[mf][nf][r] = 0.f;
    float mrow[2][2] = { {-1e30f, -1e30f}, {-1e30f, -1e30f} };
    float lrow[2][2] = { {0.f, 0.f}, {0.f, 0.f} };

    const int src0 = (lane & 28) | (lc >> 1);
    const int src1 = src0 + 2;
    const bool odd = (lc & 1);

    for (int kt = 0; kt < SEQ / 64; kt++) {
        const float* kg = kbase + (size_t)kt * 64 * DK;
        const float* vg = vbase + (size_t)kt * 64 * DK;

        __syncthreads();     // also covers Q init on first iter
#pragma unroll
        for (int it = 0; it < 8; it++) {
            int i = tid + it * 128;          // float4 index, 1024 per tensor
            int r = i >> 4, c4 = (i & 15) << 2;
            float4 a = *(const float4*)&kg[(size_t)r * DK + c4];
            uint4 ua = { f2tf(a.x), f2tf(a.y), f2tf(a.z), f2tf(a.w) };
            *(uint4*)&Ks[r * QS_STR + c4] = ua;
            float4 b = *(const float4*)&vg[(size_t)r * DK + c4];
            uint4 ub = { f2tf(b.x), f2tf(b.y), f2tf(b.z), f2tf(b.w) };
            *(uint4*)&Vs[r * VS_STR + c4] = ub;
        }
        __syncthreads();

        // S = Qs @ Ks^T  (per warp: 32x64)
        float ps[2][8][4];
#pragma unroll
        for (int mf = 0; mf < 2; mf++)
#pragma unroll
            for (int nf = 0; nf < 8; nf++)
#pragma unroll
                for (int r = 0; r < 4; r++) ps[mf][nf][r] = 0.f;

#pragma unroll
        for (int kf = 0; kf < 8; kf++) {
            uint32_t a[2][4];
#pragma unroll
            for (int mf = 0; mf < 2; mf++) {
                int row = wrow + mf * 16;
                a[mf][0] = Qs[(row + gr) * QS_STR + kf * 8 + lc];
                a[mf][1] = Qs[(row + 8 + gr) * QS_STR + kf * 8 + lc];
                a[mf][2] = Qs[(row + gr) * QS_STR + kf * 8 + lc + 4];
                a[mf][3] = Qs[(row + 8 + gr) * QS_STR + kf * 8 + lc + 4];
            }
#pragma unroll
            for (int nf = 0; nf < 8; nf++) {
                uint32_t b0 = Ks[(nf * 8 + gr) * QS_STR + kf * 8 + lc];
                uint32_t b1 = Ks[(nf * 8 + gr) * QS_STR + kf * 8 + lc + 4];
                MMA_TF32(ps[0][nf], a[0][0], a[0][1], a[0][2], a[0][3], b0, b1);
                MMA_TF32(ps[1][nf], a[1][0], a[1][1], a[1][2], a[1][3], b0, b1);
            }
        }

        // Online softmax; ps overwritten in-place with tf32(P) bit patterns
#pragma unroll
        for (int mf = 0; mf < 2; mf++) {
#pragma unroll
            for (int h = 0; h < 2; h++) {
                float mx = -1e30f;
#pragma unroll
                for (int nf = 0; nf < 8; nf++)
                    mx = fmaxf(mx, fmaxf(ps[mf][nf][2*h], ps[mf][nf][2*h+1]));
                mx = fmaxf(mx, __shfl_xor_sync(0xffffffffu, mx, 1));
                mx = fmaxf(mx, __shfl_xor_sync(0xffffffffu, mx, 2));
                float mnew = fmaxf(mrow[mf][h], mx);
                float corr = __expf(mrow[mf][h] - mnew);
                float sum = 0.f;
#pragma unroll
                for (int nf = 0; nf < 8; nf++) {
                    float p0 = __expf(ps[mf][nf][2*h]   - mnew);
                    float p1 = __expf(ps[mf][nf][2*h+1] - mnew);
                    sum += p0 + p1;
                    ps[mf][nf][2*h]   = __uint_as_float(f2tf(p0));
                    ps[mf][nf][2*h+1] = __uint_as_float(f2tf(p1));
                }
                sum += __shfl_xor_sync(0xffffffffu, sum, 1);
                sum += __shfl_xor_sync(0xffffffffu, sum, 2);
                lrow[mf][h] = lrow[mf][h] * corr + sum;
                mrow[mf][h] = mnew;
#pragma unroll
                for (int nf = 0; nf < 8; nf++) {
                    o[mf][nf][2*h]   *= corr;
                    o[mf][nf][2*h+1] *= corr;
                }
            }
        }

        // O += P @ V    (P C-frag -> A-frag via lane shuffles)
#pragma unroll
        for (int kf = 0; kf < 8; kf++) {
            uint32_t pa[2][4];
#pragma unroll
            for (int mf = 0; mf < 2; mf++) {
                float x0 = __shfl_sync(0xffffffffu, ps[mf][kf][0], src0);
                float x1 = __shfl_sync(0xffffffffu, ps[mf][kf][1], src0);
                float x2 = __shfl_sync(0xffffffffu, ps[mf][kf][2], src0);
                float x3 = __shfl_sync(0xffffffffu, ps[mf][kf][3], src0);
                float y0 = __shfl_sync(0xffffffffu, ps[mf][kf][0], src1);
                float y1 = __shfl_sync(0xffffffffu, ps[mf][kf][1], src1);
                float y2 = __shfl_sync(0xffffffffu, ps[mf][kf][2], src1);
                float y3 = __shfl_sync(0xffffffffu, ps[mf][kf][3], src1);
                pa[mf][0] = __float_as_uint(odd ? x1 : x0);
                pa[mf][1] = __float_as_uint(odd ? x3 : x2);
                pa[mf][2] = __float_as_uint(odd ? y1 : y0);
                pa[mf][3] = __float_as_uint(odd ? y3 : y2);
            }
#pragma unroll
            for (int nf = 0; nf < 8; nf++) {
                uint32_t b0 = Vs[(kf * 8 + lc) * VS_STR + nf * 8 + gr];
                uint32_t b1 = Vs[(kf * 8 + lc + 4) * VS_STR + nf * 8 + gr];
                MMA_TF32(o[0][nf], pa[0][0], pa[0][1], pa[0][2], pa[0][3], b0, b1);
                MMA_TF32(o[1][nf], pa[1][0], pa[1][1], pa[1][2], pa[1][3], b0, b1);
            }
        }
    }

    // epilogue: ctx[B,S,NH*DK]
    const int bb = bh >> 4;
    const int h_head = bh & (NH - 1);
#pragma unroll
    for (int mf = 0; mf < 2; mf++) {
#pragma unroll
        for (int half = 0; half < 2; half++) {
            float inv = 1.f / lrow[mf][half];
            int qrow = q0 + wrow + mf * 16 + half * 8 + gr;
            float* base = g_ctx + ((size_t)bb * SEQ + qrow) * (NH * DK)
                                + h_head * DK + lc * 2;
#pragma unroll
            for (int nf = 0; nf < 8; nf++) {
                float2 v = { o[mf][nf][2*half] * inv, o[mf][nf][2*half+1] * inv };
                *(float2*)(base + nf * 8) = v;
            }
        }
    }
}

// ---------------------------------------------------------------------------
extern "C" void kernel_launch(void* const* d_in, const int* in_sizes, int n_in,
                              void* d_out, int out_size)
{
    const float* x  = (const float*)d_in[0];
    const float* W1 = (const float*)d_in[1];
    const float* b1 = (const float*)d_in[2];
    const float* W2 = (const float*)d_in[3];
    const float* b2 = (const float*)d_in[4];
    float* out = (float*)d_out;

    // 1) QKV projection (tf32 mma.sync): x @ W1 + b1 -> q/k/v scratch
    mma_gemm<<<dim3(QKV_N / 128, MROWS / 128), 256>>>(x, W1, b1, nullptr,
                                                      QKV_N, HID, 0);

    // 2) tensor-core flash attention -> g_ctx
    size_t smem_bytes = (size_t)ATTN_SMEM_WORDS * sizeof(uint32_t);
    cudaFuncSetAttribute(attn_mma,
                         cudaFuncAttributeMaxDynamicSharedMemorySize,
                         (int)smem_bytes);
    attn_mma<<<dim3(SEQ / 128, BATCH * NH), 128, smem_bytes>>>();

    // 3) output projection (tf32 mma.sync): g_ctx @ W2 + b2 -> out
    mma_gemm<<<dim3(HID / 128, MROWS / 128), 256>>>(nullptr, W2, b2, out,
                                                    HID, HID, 1);
}

// round 5
// speedup vs baseline: 5.8468x; 1.6249x over previous
#include <cuda_runtime.h>
#include <cuda_fp16.h>
#include <cstdint>

// Problem constants
#define BATCH 4
#define SEQ   2048
#define HID   1024
#define NH    16
#define DK    64
#define MROWS (BATCH*SEQ)          // 8192
#define QKV_N (3*NH*DK)            // 3072

// fp16-packed scratch (u32 = half2). q/k/v: [b*NH+h][s][d2], d2 = d/2 (32 per row)
__device__ uint32_t g_qh[(size_t)BATCH*NH*SEQ*32];
__device__ uint32_t g_kh[(size_t)BATCH*NH*SEQ*32];
__device__ uint32_t g_vh[(size_t)BATCH*NH*SEQ*32];
__device__ uint32_t g_ctxh[(size_t)MROWS*512];      // [m][k2], k2 = 0..511

__device__ __forceinline__ uint32_t h2(float lo, float hi) {
    __half2 h = __floats2half2_rn(lo, hi);
    return *(uint32_t*)&h;
}

#define MMA_F16(d, a0,a1,a2,a3, b0,b1) \
    asm volatile( \
        "mma.sync.aligned.m16n8k16.row.col.f32.f16.f16.f32 " \
        "{%0,%1,%2,%3}, {%4,%5,%6,%7}, {%8,%9}, {%0,%1,%2,%3};" \
        : "+f"((d)[0]), "+f"((d)[1]), "+f"((d)[2]), "+f"((d)[3]) \
        : "r"(a0), "r"(a1), "r"(a2), "r"(a3), "r"(b0), "r"(b1))

// ---------------------------------------------------------------------------
// fp16 mma.sync GEMM: C[M,N] = A[M,K] @ B[K,N] + bias[N]
// BM=BN=128, BK=32, 256 thr (8 warps 2x4, warp tile 64x32), double-buffered.
// As[m][k2] u32 pairs along k (stride 20: frag bank 4*(5g%8)+lc bijective).
// Bs[k2][n] u32 = {B[2k2][n],B[2k2+1][n]} (stride 136: bank 8lc+gr bijective).
// mode 0: A=x fp32, epilogue -> g_qh/g_kh/g_vh (q scaled 0.125).
// mode 1: A=g_ctxh fp16-packed, epilogue -> fp32 C.
// ---------------------------------------------------------------------------
__global__ __launch_bounds__(256, 2)
void mma_gemm(const float* __restrict__ A_f32, const float* __restrict__ B,
              const float* __restrict__ bias, float* __restrict__ C,
              int N, int K, int mode)
{
    __shared__ uint32_t As[2][128][20];
    __shared__ uint32_t Bs[2][16][136];

    const int tid = threadIdx.x;
    const int lane = tid & 31;
    const int wid = tid >> 5;
    const int wm = (wid & 1) * 64;
    const int wn = (wid >> 1) * 32;
    const int gr = lane >> 2;
    const int lc = lane & 3;
    const int rowBase = blockIdx.y * 128;
    const int colBase = blockIdx.x * 128;

    float acc[4][4][4];
#pragma unroll
    for (int i = 0; i < 4; i++)
#pragma unroll
        for (int j = 0; j < 4; j++)
#pragma unroll
            for (int r = 0; r < 4; r++) acc[i][j][r] = 0.f;

    const int a_r = tid >> 3;          // 0..31 (+32/it)
    const int a_c2 = (tid & 7) * 2;    // u32 col
    const int b_n = (tid & 31) * 4;
    const int b_k2 = tid >> 5;         // 0..7 (+8/it)

    float4 pa[4]; uint2 pah[4];
    float4 pbe[2], pbo[2];

    const int KT = K / 32;

    auto ldAB = [&](int kt) {
        if (mode == 0) {
#pragma unroll
            for (int it = 0; it < 4; it++)
                pa[it] = *(const float4*)&A_f32[(size_t)(rowBase + a_r + it * 32) * K
                                                + kt * 32 + (tid & 7) * 4];
        } else {
#pragma unroll
            for (int it = 0; it < 4; it++)
                pah[it] = *(const uint2*)&g_ctxh[(size_t)(rowBase + a_r + it * 32) * 512
                                                 + kt * 16 + a_c2];
        }
#pragma unroll
        for (int it = 0; it < 2; it++) {
            int k2 = b_k2 + it * 8;
            pbe[it] = *(const float4*)&B[(size_t)(kt * 32 + 2 * k2) * N + colBase + b_n];
            pbo[it] = *(const float4*)&B[(size_t)(kt * 32 + 2 * k2 + 1) * N + colBase + b_n];
        }
    };
    auto sts = [&](int buf) {
#pragma unroll
        for (int it = 0; it < 4; it++) {
            uint2 u;
            if (mode == 0) u = make_uint2(h2(pa[it].x, pa[it].y), h2(pa[it].z, pa[it].w));
            else           u = pah[it];
            *(uint2*)&As[buf][a_r + it * 32][a_c2] = u;
        }
#pragma unroll
        for (int it = 0; it < 2; it++) {
            uint4 u = { h2(pbe[it].x, pbo[it].x), h2(pbe[it].y, pbo[it].y),
                        h2(pbe[it].z, pbo[it].z), h2(pbe[it].w, pbo[it].w) };
            *(uint4*)&Bs[buf][b_k2 + it * 8][b_n] = u;
        }
    };

    ldAB(0);
    sts(0);
    __syncthreads();

    for (int kt = 0; kt < KT; kt++) {
        const int buf = kt & 1;
        if (kt + 1 < KT) ldAB(kt + 1);

#pragma unroll
        for (int c = 0; c < 2; c++) {
            uint32_t af[4][4], bf[4][2];
#pragma unroll
            for (int mf = 0; mf < 4; mf++) {
                int m = wm + mf * 16;
                af[mf][0] = As[buf][m + gr][c * 8 + lc];
                af[mf][1] = As[buf][m + 8 + gr][c * 8 + lc];
                af[mf][2] = As[buf][m + gr][c * 8 + lc + 4];
                af[mf][3] = As[buf][m + 8 + gr][c * 8 + lc + 4];
            }
#pragma unroll
            for (int nf = 0; nf < 4; nf++) {
                int n = wn + nf * 8 + gr;
                bf[nf][0] = Bs[buf][c * 8 + lc][n];
                bf[nf][1] = Bs[buf][c * 8 + lc + 4][n];
            }
#pragma unroll
            for (int mf = 0; mf < 4; mf++)
#pragma unroll
                for (int nf = 0; nf < 4; nf++)
                    MMA_F16(acc[mf][nf], af[mf][0], af[mf][1], af[mf][2], af[mf][3],
                            bf[nf][0], bf[nf][1]);
        }
        if (kt + 1 < KT) { sts((kt + 1) & 1); __syncthreads(); }
    }

#pragma unroll
    for (int mf = 0; mf < 4; mf++) {
#pragma unroll
        for (int nf = 0; nf < 4; nf++) {
            int m0 = rowBase + wm + mf * 16 + gr;
            int n0 = colBase + wn + nf * 8 + lc * 2;
            float bi0 = bias[n0], bi1 = bias[n0 + 1];
            if (mode == 0) {
                int qkv = n0 >> 10;
                int h = (n0 >> 6) & (NH - 1);
                int d2 = (n0 & 63) >> 1;
                float sc = (qkv == 0) ? 0.125f : 1.f;
                uint32_t* dst = (qkv == 0) ? g_qh : (qkv == 1) ? g_kh : g_vh;
#pragma unroll
                for (int half = 0; half < 2; half++) {
                    int m = m0 + half * 8;
                    int bb = m >> 11, ss = m & (SEQ - 1);
                    float v0 = (acc[mf][nf][half * 2 + 0] + bi0) * sc;
                    float v1 = (acc[mf][nf][half * 2 + 1] + bi1) * sc;
                    dst[(((size_t)bb * NH + h) * SEQ + ss) * 32 + d2] = h2(v0, v1);
                }
            } else {
#pragma unroll
                for (int half = 0; half < 2; half++) {
                    int m = m0 + half * 8;
                    float* p = C + (size_t)m * N + n0;
                    p[0] = acc[mf][nf][half * 2 + 0] + bi0;
                    p[1] = acc[mf][nf][half * 2 + 1] + bi1;
                }
            }
        }
    }
}

// ---------------------------------------------------------------------------
// fp16 tensor-core flash attention. 128 thr = 4 warps; warp = 32 q-rows x 64.
// BQ=128, BK=64, 32 k-tiles. All operands fp16-packed u32 from gmem.
// Qs/Ks stride 36 (frag bank 4g+lc bij), Vs stride 72 (bank 8lc+g bij).
// P C-frags pack straight into PV A-frags (no shuffles).
// ---------------------------------------------------------------------------
__global__ __launch_bounds__(128, 2)
void attn_mma()
{
    __shared__ uint32_t Qs[128][36];   // [q][d2]
    __shared__ uint32_t Ks[64][36];    // [key][d2]
    __shared__ uint32_t Vs[32][72];    // [key2][d], u32 = {V[2k2][d],V[2k2+1][d]}

    const int tid = threadIdx.x;
    const int lane = tid & 31;
    const int wid = tid >> 5;
    const int gr = lane >> 2;
    const int lc = lane & 3;
    const int q0 = blockIdx.x * 128;
    const int bh = blockIdx.y;
    const int wrow = wid * 32;

    const uint4* Qg4 = (const uint4*)(g_qh + ((size_t)bh * SEQ + q0) * 32);
    const uint32_t* Kg = g_kh + (size_t)bh * SEQ * 32;
    const uint32_t* Vg = g_vh + (size_t)bh * SEQ * 32;

    // Q tile: 128 rows x 8 uint4
#pragma unroll
    for (int it = 0; it < 8; it++) {
        int i = tid + it * 128;
        int r = i >> 3, c = i & 7;
        *(uint4*)&Qs[r][c * 4] = Qg4[r * 8 + c];
    }

    float o[2][8][4];
#pragma unroll
    for (int mf = 0; mf < 2; mf++)
#pragma unroll
        for (int nf = 0; nf < 8; nf++)
#pragma unroll
            for (int r = 0; r < 4; r++) o[mf][nf][r] = 0.f;
    float mrow[2][2] = { {-1e30f, -1e30f}, {-1e30f, -1e30f} };
    float lrow[2][2] = { {0.f, 0.f}, {0.f, 0.f} };

    for (int kt = 0; kt < SEQ / 64; kt++) {
        const uint4* Kt4 = (const uint4*)(Kg + (size_t)kt * 64 * 32);
        const uint4* Vt4 = (const uint4*)(Vg + (size_t)kt * 64 * 32);

        __syncthreads();    // prior tile consumed (covers Q init on kt=0)
        // K: raw copy 64x32 u32
#pragma unroll
        for (int it = 0; it < 4; it++) {
            int i = tid + it * 128;
            int r = i >> 3, c = i & 7;
            *(uint4*)&Ks[r][c * 4] = Kt4[r * 8 + c];
        }
        // V: repack (pairs along d) -> (pairs along key) via byte_perm
#pragma unroll
        for (int it = 0; it < 2; it++) {
            int i = tid + it * 128;
            int k2 = i >> 3, dg = i & 7;          // dg: group of 4 d2
            uint4 e = Vt4[(2 * k2) * 8 + dg];
            uint4 od = Vt4[(2 * k2 + 1) * 8 + dg];
            uint4 u0 = { __byte_perm(e.x, od.x, 0x5410), __byte_perm(e.x, od.x, 0x7632),
                         __byte_perm(e.y, od.y, 0x5410), __byte_perm(e.y, od.y, 0x7632) };
            uint4 u1 = { __byte_perm(e.z, od.z, 0x5410), __byte_perm(e.z, od.z, 0x7632),
                         __byte_perm(e.w, od.w, 0x5410), __byte_perm(e.w, od.w, 0x7632) };
            *(uint4*)&Vs[k2][dg * 8]     = u0;
            *(uint4*)&Vs[k2][dg * 8 + 4] = u1;
        }
        __syncthreads();

        // S = Q @ K^T (warp: 32x64), 4 k16 chunks over d
        float ps[2][8][4];
#pragma unroll
        for (int mf = 0; mf < 2; mf++)
#pragma unroll
            for (int nf = 0; nf < 8; nf++)
#pragma unroll
                for (int r = 0; r < 4; r++) ps[mf][nf][r] = 0.f;

#pragma unroll
        for (int ch = 0; ch < 4; ch++) {
            uint32_t a[2][4];
#pragma unroll
            for (int mf = 0; mf < 2; mf++) {
                int row = wrow + mf * 16;
                a[mf][0] = Qs[row + gr][ch * 8 + lc];
                a[mf][1] = Qs[row + 8 + gr][ch * 8 + lc];
                a[mf][2] = Qs[row + gr][ch * 8 + lc + 4];
                a[mf][3] = Qs[row + 8 + gr][ch * 8 + lc + 4];
            }
#pragma unroll
            for (int nf = 0; nf < 8; nf++) {
                uint32_t b0 = Ks[nf * 8 + gr][ch * 8 + lc];
                uint32_t b1 = Ks[nf * 8 + gr][ch * 8 + lc + 4];
                MMA_F16(ps[0][nf], a[0][0], a[0][1], a[0][2], a[0][3], b0, b1);
                MMA_F16(ps[1][nf], a[1][0], a[1][1], a[1][2], a[1][3], b0, b1);
            }
        }

        // Online softmax (register-resident); pack P into PV A-frag halves
        uint32_t pp[2][8][2];
#pragma unroll
        for (int mf = 0; mf < 2; mf++) {
#pragma unroll
            for (int h = 0; h < 2; h++) {
                float mx = -1e30f;
#pragma unroll
                for (int nf = 0; nf < 8; nf++)
                    mx = fmaxf(mx, fmaxf(ps[mf][nf][2*h], ps[mf][nf][2*h+1]));
                mx = fmaxf(mx, __shfl_xor_sync(0xffffffffu, mx, 1));
                mx = fmaxf(mx, __shfl_xor_sync(0xffffffffu, mx, 2));
                float mnew = fmaxf(mrow[mf][h], mx);
                float corr = __expf(mrow[mf][h] - mnew);
                float sum = 0.f;
#pragma unroll
                for (int nf = 0; nf < 8; nf++) {
                    float p0 = __expf(ps[mf][nf][2*h]   - mnew);
                    float p1 = __expf(ps[mf][nf][2*h+1] - mnew);
                    sum += p0 + p1;
                    ps[mf][nf][2*h]   = p0;
                    ps[mf][nf][2*h+1] = p1;
                }
                sum += __shfl_xor_sync(0xffffffffu, sum, 1);
                sum += __shfl_xor_sync(0xffffffffu, sum, 2);
                lrow[mf][h] = lrow[mf][h] * corr + sum;
                mrow[mf][h] = mnew;
#pragma unroll
                for (int nf = 0; nf < 8; nf++) {
                    o[mf][nf][2*h]   *= corr;
                    o[mf][nf][2*h+1] *= corr;
                }
            }
#pragma unroll
            for (int nf = 0; nf < 8; nf++) {
                pp[mf][nf][0] = h2(ps[mf][nf][0], ps[mf][nf][1]);
                pp[mf][nf][1] = h2(ps[mf][nf][2], ps[mf][nf][3]);
            }
        }

        // O += P @ V : A-frag = two adjacent C-frags, zero shuffles
#pragma unroll
        for (int kf = 0; kf < 4; kf++) {
#pragma unroll
            for (int nf = 0; nf < 8; nf++) {
                uint32_t b0 = Vs[kf * 8 + lc][nf * 8 + gr];
                uint32_t b1 = Vs[kf * 8 + lc + 4][nf * 8 + gr];
                MMA_F16(o[0][nf], pp[0][2*kf][0], pp[0][2*kf][1],
                        pp[0][2*kf+1][0], pp[0][2*kf+1][1], b0, b1);
                MMA_F16(o[1][nf], pp[1][2*kf][0], pp[1][2*kf][1],
                        pp[1][2*kf+1][0], pp[1][2*kf+1][1], b0, b1);
            }
        }
    }

    // epilogue -> g_ctxh fp16-packed [m][512]
    const int bb = bh >> 4;
    const int h_head = bh & (NH - 1);
#pragma unroll
    for (int mf = 0; mf < 2; mf++) {
#pragma unroll
        for (int half = 0; half < 2; half++) {
            float inv = 1.f / lrow[mf][half];
            int qrow = q0 + wrow + mf * 16 + half * 8 + gr;
            uint32_t* base = g_ctxh + ((size_t)bb * SEQ + qrow) * 512
                           + h_head * 32 + lc;
#pragma unroll
            for (int nf = 0; nf < 8; nf++)
                base[nf * 4] = h2(o[mf][nf][2*half] * inv,
                                  o[mf][nf][2*half+1] * inv);
        }
    }
}

// ---------------------------------------------------------------------------
extern "C" void kernel_launch(void* const* d_in, const int* in_sizes, int n_in,
                              void* d_out, int out_size)
{
    const float* x  = (const float*)d_in[0];
    const float* W1 = (const float*)d_in[1];
    const float* b1 = (const float*)d_in[2];
    const float* W2 = (const float*)d_in[3];
    const float* b2 = (const float*)d_in[4];
    float* out = (float*)d_out;

    // 1) QKV projection -> fp16-packed q/k/v (q pre-scaled by 1/8)
    mma_gemm<<<dim3(QKV_N / 128, MROWS / 128), 256>>>(x, W1, b1, nullptr,
                                                      QKV_N, HID, 0);

    // 2) fp16 tensor-core flash attention -> g_ctxh
    attn_mma<<<dim3(SEQ / 128, BATCH * NH), 128>>>();

    // 3) output projection: ctx @ W2 + b2 -> out (fp32)
    mma_gemm<<<dim3(HID / 128, MROWS / 128), 256>>>(nullptr, W2, b2, out,
                                                    HID, HID, 1);
}

// round 8
// speedup vs baseline: 8.2599x; 1.4127x over previous
#include <cuda_runtime.h>
#include <cuda_fp16.h>
#include <cstdint>

// Problem constants
#define BATCH 4
#define SEQ   2048
#define HID   1024
#define NH    16
#define DK    64
#define MROWS (BATCH*SEQ)          // 8192
#define QKV_N (3*NH*DK)            // 3072
#define K2G   512                  // K/2 (u32 half2 units) for both GEMMs

// fp16-packed scratch (u32 = half2)
__device__ uint32_t g_xh[(size_t)MROWS*K2G];        // x        [m][k2]
__device__ uint32_t g_w1h[(size_t)QKV_N*K2G];       // W1^T     [n][k2]
__device__ uint32_t g_w2h[(size_t)HID*K2G];         // W2^T     [n][k2]
__device__ uint32_t g_qh[(size_t)BATCH*NH*SEQ*32];  // [bh][s][d2]
__device__ uint32_t g_kh[(size_t)BATCH*NH*SEQ*32];  // [bh][s][d2]
__device__ uint32_t g_vh[(size_t)BATCH*NH*DK*(SEQ/2)]; // planar [bh][d][s2]
__device__ uint32_t g_ctxh[(size_t)MROWS*K2G];      // [m][k2]

__device__ __forceinline__ uint32_t h2(float lo, float hi) {
    __half2 h = __floats2half2_rn(lo, hi);
    return *(uint32_t*)&h;
}
__device__ __forceinline__ uint32_t smem_u32(const void* p) {
    uint32_t a;
    asm("{ .reg .u64 t; cvta.to.shared.u64 t, %1; cvt.u32.u64 %0, t; }"
        : "=r"(a) : "l"(p));
    return a;
}

#define MMA_F16(d, a0,a1,a2,a3, b0,b1) \
    asm volatile( \
        "mma.sync.aligned.m16n8k16.row.col.f32.f16.f16.f32 " \
        "{%0,%1,%2,%3}, {%4,%5,%6,%7}, {%8,%9}, {%0,%1,%2,%3};" \
        : "+f"((d)[0]), "+f"((d)[1]), "+f"((d)[2]), "+f"((d)[3]) \
        : "r"(a0), "r"(a1), "r"(a2), "r"(a3), "r"(b0), "r"(b1))

#define LDSM4(r0,r1,r2,r3, addr) \
    asm volatile("ldmatrix.sync.aligned.m8n8.x4.shared.b16 {%0,%1,%2,%3}, [%4];" \
        : "=r"(r0), "=r"(r1), "=r"(r2), "=r"(r3) : "r"(addr))

#define CP16(dst, src) \
    asm volatile("cp.async.cg.shared.global [%0], [%1], 16;" :: "r"(dst), "l"(src))
#define CP_COMMIT() asm volatile("cp.async.commit_group;")
#define CP_WAIT0()  asm volatile("cp.async.wait_group 0;")

// ---------------------------------------------------------------------------
// Converters (run once per launch; ~15us total)
// ---------------------------------------------------------------------------
__global__ void cvt_x(const float* __restrict__ x)
{
    size_t i = (size_t)blockIdx.x * 256 + threadIdx.x;   // float4 index
    float4 v = ((const float4*)x)[i];
    ((uint2*)g_xh)[i] = make_uint2(h2(v.x, v.y), h2(v.z, v.w));
}

// W[K=1024][Ncols] fp32 -> dst[n][512] u32 (transposed, pairs along k)
__global__ void cvt_w(const float* __restrict__ W, int Ncols, int which)
{
    uint32_t* dst = which ? g_w2h : g_w1h;
    __shared__ float t[32][33];
    int n0 = blockIdx.x * 32, k0 = blockIdx.y * 32;
    int tx = threadIdx.x, ty = threadIdx.y;
#pragma unroll
    for (int r = ty; r < 32; r += 8)
        t[r][tx] = W[(size_t)(k0 + r) * Ncols + n0 + tx];
    __syncthreads();
#pragma unroll
    for (int r = ty; r < 32; r += 8)
        if (tx < 16)
            dst[(size_t)(n0 + r) * K2G + (k0 >> 1) + tx] =
                h2(t[2 * tx][r], t[2 * tx + 1][r]);
}

// ---------------------------------------------------------------------------
// fp16 GEMM, cp.async double-buffered + ldmatrix fragments.
// C[M,N] = A[M,K] @ B^T[N,K]^T + bias. A,B fp16-packed K-major [rows][k2].
// BM=BN=128, BK=32 (16 u32/row/tile), 256 thr (8 warps 2x4, 64x32 warp tile).
// mode 0: A=g_xh, B=g_w1h, scatter q/k/v (q*0.125, v planar).
// mode 1: A=g_ctxh, B=g_w2h, fp32 C out.
// ---------------------------------------------------------------------------
__global__ __launch_bounds__(256, 2)
void mma_gemm(const float* __restrict__ bias, float* __restrict__ C,
              int N, int mode)
{
    __shared__ uint32_t As[2][128][20];
    __shared__ uint32_t Bs[2][128][20];

    const uint32_t* Ah = mode ? g_ctxh : g_xh;
    const uint32_t* Bh = mode ? g_w2h : g_w1h;

    const int tid = threadIdx.x;
    const int lane = tid & 31;
    const int wid = tid >> 5;
    const int wm = (wid & 1) * 64;
    const int wn = (wid >> 1) * 32;
    const int gr = lane >> 4 ? 0 : 0;  (void)gr;
    const int rowBase = blockIdx.y * 128;
    const int colBase = blockIdx.x * 128;

    // ldmatrix lane addressing
    const int arow = ((lane >> 3) & 1) * 8 + (lane & 7);
    const int acol = ((lane >> 4) & 1) * 4;
    const int brow = ((lane >> 4) & 1) * 8 + (lane & 7);
    const int bcol = ((lane >> 3) & 1) * 4;

    // cp.async mapping: 512 16B-chunks per operand, 2 per thread
    const int cr = tid >> 2;           // row 0..63 (+64)
    const int co = (tid & 3) * 4;      // u32 offset in row slice
    const uint32_t* Asrc0 = Ah + (size_t)(rowBase + cr) * K2G + co;
    const uint32_t* Asrc1 = Ah + (size_t)(rowBase + cr + 64) * K2G + co;
    const uint32_t* Bsrc0 = Bh + (size_t)(colBase + cr) * K2G + co;
    const uint32_t* Bsrc1 = Bh + (size_t)(colBase + cr + 64) * K2G + co;
    const uint32_t asb = smem_u32(As);
    const uint32_t bsb = smem_u32(Bs);
    const uint32_t dA0 = asb + (cr * 20 + co) * 4;
    const uint32_t dA1 = asb + ((cr + 64) * 20 + co) * 4;
    const uint32_t dB0 = bsb + (cr * 20 + co) * 4;
    const uint32_t dB1 = bsb + ((cr + 64) * 20 + co) * 4;

    float acc[4][4][4];
#pragma unroll
    for (int i = 0; i < 4; i++)
#pragma unroll
        for (int j = 0; j < 4; j++)
#pragma unroll
            for (int r = 0; r < 4; r++) acc[i][j][r] = 0.f;

    auto prefetch = [&](int s, int kt) {
        uint32_t so = s * 2560 * 4;
        CP16(dA0 + so, Asrc0 + kt * 16);
        CP16(dA1 + so, Asrc1 + kt * 16);
        CP16(dB0 + so, Bsrc0 + kt * 16);
        CP16(dB1 + so, Bsrc1 + kt * 16);
        CP_COMMIT();
    };

    prefetch(0, 0);
    const int KT = 32;
    for (int kt = 0; kt < KT; kt++) {
        const int s = kt & 1;
        CP_WAIT0();
        __syncthreads();
        if (kt + 1 < KT) prefetch(s ^ 1, kt + 1);

        const uint32_t sa = asb + s * 2560 * 4;
        const uint32_t sb = bsb + s * 2560 * 4;
#pragma unroll
        for (int c = 0; c < 2; c++) {
            uint32_t af[4][4], bf[4][2];
#pragma unroll
            for (int mf = 0; mf < 4; mf++)
                LDSM4(af[mf][0], af[mf][1], af[mf][2], af[mf][3],
                      sa + ((wm + mf * 16 + arow) * 20 + c * 8 + acol) * 4);
#pragma unroll
            for (int np = 0; np < 2; np++)
                LDSM4(bf[2*np][0], bf[2*np][1], bf[2*np+1][0], bf[2*np+1][1],
                      sb + ((wn + np * 16 + brow) * 20 + c * 8 + bcol) * 4);
#pragma unroll
            for (int mf = 0; mf < 4; mf++)
#pragma unroll
                for (int nf = 0; nf < 4; nf++)
                    MMA_F16(acc[mf][nf], af[mf][0], af[mf][1], af[mf][2], af[mf][3],
                            bf[nf][0], bf[nf][1]);
        }
        __syncthreads();
    }

    // epilogue
    const int egr = lane >> 2;
    const int elc = lane & 3;
#pragma unroll
    for (int mf = 0; mf < 4; mf++) {
#pragma unroll
        for (int nf = 0; nf < 4; nf++) {
            int m0 = rowBase + wm + mf * 16 + egr;
            int n0 = colBase + wn + nf * 8 + elc * 2;
            float bi0 = bias[n0], bi1 = bias[n0 + 1];
            if (mode == 0) {
                int qkv = n0 >> 10;
                int h = (n0 >> 6) & (NH - 1);
                if (qkv == 2) {
                    int d = n0 & 63;
                    __half* vh = (__half*)g_vh;
#pragma unroll
                    for (int half = 0; half < 2; half++) {
                        int m = m0 + half * 8;
                        int bb = m >> 11, ss = m & (SEQ - 1);
                        size_t base = ((size_t)(bb * NH + h) * DK + d) * SEQ + ss;
                        vh[base]       = __float2half(acc[mf][nf][half*2+0] + bi0);
                        vh[base + SEQ] = __float2half(acc[mf][nf][half*2+1] + bi1);
                    }
                } else {
                    int d2 = (n0 & 63) >> 1;
                    float sc = (qkv == 0) ? 0.125f : 1.f;
                    uint32_t* dst = (qkv == 0) ? g_qh : g_kh;
#pragma unroll
                    for (int half = 0; half < 2; half++) {
                        int m = m0 + half * 8;
                        int bb = m >> 11, ss = m & (SEQ - 1);
                        dst[(((size_t)bb * NH + h) * SEQ + ss) * 32 + d2] =
                            h2((acc[mf][nf][half*2+0] + bi0) * sc,
                               (acc[mf][nf][half*2+1] + bi1) * sc);
                    }
                }
            } else {
#pragma unroll
                for (int half = 0; half < 2; half++) {
                    int m = m0 + half * 8;
                    float* p = C + (size_t)m * N + n0;
                    p[0] = acc[mf][nf][half*2+0] + bi0;
                    p[1] = acc[mf][nf][half*2+1] + bi1;
                }
            }
        }
    }
}

// ---------------------------------------------------------------------------
// fp16 flash attention: cp.async double-buffered K/V, ldmatrix frags,
// planar V (no repack), register softmax, P->A-frag by packing.
// 128 thr = 4 warps; warp = 32 q x 64; BQ=128, BK=64, 32 tiles.
// smem u32: Qs[128][36] | Ks[2][64][36] | Vs[2][64][36]  (55296 B)
// ---------------------------------------------------------------------------
#define ATTN_SMEM_BYTES ((4608 + 2*2304 + 2*2304) * 4)

__global__ __launch_bounds__(128, 2)
void attn_mma()
{
    extern __shared__ uint32_t sm[];
    uint32_t* Qs = sm;                 // [128][36]
    uint32_t* Ks = sm + 4608;          // [2][64][36]
    uint32_t* Vs = sm + 4608 + 4608;   // [2][64][36]

    const int tid = threadIdx.x;
    const int lane = tid & 31;
    const int wid = tid >> 5;
    const int gr = lane >> 2;
    const int lc = lane & 3;
    const int q0 = blockIdx.x * 128;
    const int bh = blockIdx.y;
    const int wrow = wid * 32;

    const int arow = ((lane >> 3) & 1) * 8 + (lane & 7);
    const int acol = ((lane >> 4) & 1) * 4;
    const int brow = ((lane >> 4) & 1) * 8 + (lane & 7);
    const int bcol = ((lane >> 3) & 1) * 4;

    const uint32_t qsb = smem_u32(Qs);
    const uint32_t ksb = smem_u32(Ks);
    const uint32_t vsb = smem_u32(Vs);

    const uint32_t* Kg = g_kh + (size_t)bh * SEQ * 32;
    const uint32_t* Vg = g_vh + (size_t)bh * DK * (SEQ / 2);

    // Q tile once: 128 rows x 8 uint4
    {
        const uint4* Qg4 = (const uint4*)(g_qh + ((size_t)bh * SEQ + q0) * 32);
#pragma unroll
        for (int it = 0; it < 8; it++) {
            int i = tid + it * 128;
            int r = i >> 3, c = i & 7;
            *(uint4*)((char*)sm + (qsb - smem_u32(sm)) + (r * 36 + c * 4) * 4) = Qg4[r * 8 + c];
        }
    }

    // cp.async mapping: K/V tiles 64 rows x 32 u32 = 512 chunks, 4/thread
    const int cr = tid >> 3;           // row 0..15 (+16 per it? no: c>>3 with c up to 511)
    const int co = (tid & 7) * 4;
    auto prefetch = [&](int s, int kt) {
#pragma unroll
        for (int i = 0; i < 4; i++) {
            int c = tid + i * 128;
            int row = c >> 3, off = (c & 7) * 4;
            CP16(ksb + (s * 2304 + row * 36 + off) * 4,
                 Kg + ((size_t)(kt * 64 + row)) * 32 + off);
            CP16(vsb + (s * 2304 + row * 36 + off) * 4,
                 Vg + (size_t)row * (SEQ / 2) + kt * 32 + off);
        }
        CP_COMMIT();
    };
    (void)cr; (void)co;

    float o[2][8][4];
#pragma unroll
    for (int mf = 0; mf < 2; mf++)
#pragma unroll
        for (int nf = 0; nf < 8; nf++)
#pragma unroll
            for (int r = 0; r < 4; r++) o[mf][nf][r] = 0.f;
    float mrow[2][2] = { {-1e30f, -1e30f}, {-1e30f, -1e30f} };
    float lrow[2][2] = { {0.f, 0.f}, {0.f, 0.f} };

    prefetch(0, 0);
    const int NT = SEQ / 64;
    for (int kt = 0; kt < NT; kt++) {
        const int s = kt & 1;
        CP_WAIT0();
        __syncthreads();
        if (kt + 1 < NT) prefetch(s ^ 1, kt + 1);

        // S = Q @ K^T
        float ps[2][8][4];
#pragma unroll
        for (int mf = 0; mf < 2; mf++)
#pragma unroll
            for (int nf = 0; nf < 8; nf++)
#pragma unroll
                for (int r = 0; r < 4; r++) ps[mf][nf][r] = 0.f;

#pragma unroll
        for (int ch = 0; ch < 4; ch++) {
            uint32_t a[2][4], bK[8][2];
#pragma unroll
            for (int mf = 0; mf < 2; mf++)
                LDSM4(a[mf][0], a[mf][1], a[mf][2], a[mf][3],
                      qsb + ((wrow + mf * 16 + arow) * 36 + ch * 8 + acol) * 4);
#pragma unroll
            for (int np = 0; np < 4; np++)
                LDSM4(bK[2*np][0], bK[2*np][1], bK[2*np+1][0], bK[2*np+1][1],
                      ksb + (s * 2304 + (np * 16 + brow) * 36 + ch * 8 + bcol) * 4);
#pragma unroll
            for (int nf = 0; nf < 8; nf++) {
                MMA_F16(ps[0][nf], a[0][0], a[0][1], a[0][2], a[0][3],
                        bK[nf][0], bK[nf][1]);
                MMA_F16(ps[1][nf], a[1][0], a[1][1], a[1][2], a[1][3],
                        bK[nf][0], bK[nf][1]);
            }
        }

        // Online softmax + pack P
        uint32_t pp[2][8][2];
#pragma unroll
        for (int mf = 0; mf < 2; mf++) {
#pragma unroll
            for (int h = 0; h < 2; h++) {
                float mx = -1e30f;
#pragma unroll
                for (int nf = 0; nf < 8; nf++)
                    mx = fmaxf(mx, fmaxf(ps[mf][nf][2*h], ps[mf][nf][2*h+1]));
                mx = fmaxf(mx, __shfl_xor_sync(0xffffffffu, mx, 1));
                mx = fmaxf(mx, __shfl_xor_sync(0xffffffffu, mx, 2));
                float mnew = fmaxf(mrow[mf][h], mx);
                float corr = __expf(mrow[mf][h] - mnew);
                float sum = 0.f;
#pragma unroll
                for (int nf = 0; nf < 8; nf++) {
                    float p0 = __expf(ps[mf][nf][2*h]   - mnew);
                    float p1 = __expf(ps[mf][nf][2*h+1] - mnew);
                    sum += p0 + p1;
                    ps[mf][nf][2*h]   = p0;
                    ps[mf][nf][2*h+1] = p1;
                }
                sum += __shfl_xor_sync(0xffffffffu, sum, 1);
                sum += __shfl_xor_sync(0xffffffffu, sum, 2);
                lrow[mf][h] = lrow[mf][h] * corr + sum;
                mrow[mf][h] = mnew;
#pragma unroll
                for (int nf = 0; nf < 8; nf++) {
                    o[mf][nf][2*h]   *= corr;
                    o[mf][nf][2*h+1] *= corr;
                }
            }
#pragma unroll
            for (int nf = 0; nf < 8; nf++) {
                pp[mf][nf][0] = h2(ps[mf][nf][0], ps[mf][nf][1]);
                pp[mf][nf][1] = h2(ps[mf][nf][2], ps[mf][nf][3]);
            }
        }

        // O += P @ V  (V planar: rows=d, cols=s2)
#pragma unroll
        for (int kf = 0; kf < 4; kf++) {
            uint32_t bV[8][2];
#pragma unroll
            for (int np = 0; np < 4; np++)
                LDSM4(bV[2*np][0], bV[2*np][1], bV[2*np+1][0], bV[2*np+1][1],
                      vsb + (s * 2304 + (np * 16 + brow) * 36 + kf * 8 + bcol) * 4);
#pragma unroll
            for (int nf = 0; nf < 8; nf++) {
                MMA_F16(o[0][nf], pp[0][2*kf][0], pp[0][2*kf][1],
                        pp[0][2*kf+1][0], pp[0][2*kf+1][1], bV[nf][0], bV[nf][1]);
                MMA_F16(o[1][nf], pp[1][2*kf][0], pp[1][2*kf][1],
                        pp[1][2*kf+1][0], pp[1][2*kf+1][1], bV[nf][0], bV[nf][1]);
            }
        }
        __syncthreads();
    }

    // epilogue -> g_ctxh fp16-packed [m][512]
    const int bb = bh >> 4;
    const int h_head = bh & (NH - 1);
#pragma unroll
    for (int mf = 0; mf < 2; mf++) {
#pragma unroll
        for (int half = 0; half < 2; half++) {
            float inv = 1.f / lrow[mf][half];
            int qrow = q0 + wrow + mf * 16 + half * 8 + gr;
            uint32_t* base = g_ctxh + ((size_t)bb * SEQ + qrow) * K2G
                           + h_head * 32 + lc;
#pragma unroll
            for (int nf = 0; nf < 8; nf++)
                base[nf * 4] = h2(o[mf][nf][2*half] * inv,
                                  o[mf][nf][2*half+1] * inv);
        }
    }
}

// ---------------------------------------------------------------------------
extern "C" void kernel_launch(void* const* d_in, const int* in_sizes, int n_in,
                              void* d_out, int out_size)
{
    const float* x  = (const float*)d_in[0];
    const float* W1 = (const float*)d_in[1];
    const float* b1 = (const float*)d_in[2];
    const float* W2 = (const float*)d_in[3];
    const float* b2 = (const float*)d_in[4];
    float* out = (float*)d_out;

    // 0) converters
    cvt_x<<<MROWS * HID / 4 / 256, 256>>>(x);
    cvt_w<<<dim3(QKV_N / 32, HID / 32), dim3(32, 8)>>>(W1, QKV_N, 0);
    cvt_w<<<dim3(HID / 32, HID / 32), dim3(32, 8)>>>(W2, HID, 1);

    // 1) QKV projection -> q/k (interleaved) + v (planar), q pre-scaled
    mma_gemm<<<dim3(QKV_N / 128, MROWS / 128), 256>>>(b1, nullptr, QKV_N, 0);

    // 2) flash attention -> g_ctxh
    cudaFuncSetAttribute(attn_mma,
                         cudaFuncAttributeMaxDynamicSharedMemorySize,
                         ATTN_SMEM_BYTES);
    attn_mma<<<dim3(SEQ / 128, BATCH * NH), 128, ATTN_SMEM_BYTES>>>();

    // 3) output projection -> fp32 out
    mma_gemm<<<dim3(HID / 128, MROWS / 128), 256>>>(b2, out, HID, 1);
}

// round 9
// speedup vs baseline: 8.6673x; 1.0493x over previous
#include <cuda_runtime.h>
#include <cuda_fp16.h>
#include <cstdint>

// Problem constants
#define BATCH 4
#define SEQ   2048
#define HID   1024
#define NH    16
#define DK    64
#define MROWS (BATCH*SEQ)          // 8192
#define QKV_N (3*NH*DK)            // 3072
#define K2G   512                  // K/2 (u32 half2 units) for both GEMMs
#define LOG2E 1.4426950408889634f

// fp16-packed scratch (u32 = half2)
__device__ uint32_t g_xh[(size_t)MROWS*K2G];        // x        [m][k2]
__device__ uint32_t g_w1h[(size_t)QKV_N*K2G];       // W1^T     [n][k2]
__device__ uint32_t g_w2h[(size_t)HID*K2G];         // W2^T     [n][k2]
__device__ uint32_t g_qh[(size_t)BATCH*NH*SEQ*32];  // [bh][s][d2]
__device__ uint32_t g_kh[(size_t)BATCH*NH*SEQ*32];  // [bh][s][d2]
__device__ uint32_t g_vh[(size_t)BATCH*NH*DK*(SEQ/2)]; // planar [bh][d][s2]
__device__ uint32_t g_ctxh[(size_t)MROWS*K2G];      // [m][k2]

__device__ __forceinline__ uint32_t h2(float lo, float hi) {
    __half2 h = __floats2half2_rn(lo, hi);
    return *(uint32_t*)&h;
}
__device__ __forceinline__ uint32_t smem_u32(const void* p) {
    uint32_t a;
    asm("{ .reg .u64 t; cvta.to.shared.u64 t, %1; cvt.u32.u64 %0, t; }"
        : "=r"(a) : "l"(p));
    return a;
}

#define MMA_F16(d, a0,a1,a2,a3, b0,b1) \
    asm volatile( \
        "mma.sync.aligned.m16n8k16.row.col.f32.f16.f16.f32 " \
        "{%0,%1,%2,%3}, {%4,%5,%6,%7}, {%8,%9}, {%0,%1,%2,%3};" \
        : "+f"((d)[0]), "+f"((d)[1]), "+f"((d)[2]), "+f"((d)[3]) \
        : "r"(a0), "r"(a1), "r"(a2), "r"(a3), "r"(b0), "r"(b1))

#define LDSM4(r0,r1,r2,r3, addr) \
    asm volatile("ldmatrix.sync.aligned.m8n8.x4.shared.b16 {%0,%1,%2,%3}, [%4];" \
        : "=r"(r0), "=r"(r1), "=r"(r2), "=r"(r3) : "r"(addr))

#define CP16(dst, src) \
    asm volatile("cp.async.cg.shared.global [%0], [%1], 16;" :: "r"(dst), "l"(src))
#define CP_COMMIT()  asm volatile("cp.async.commit_group;")
#define CP_WAIT(n)   asm volatile("cp.async.wait_group %0;" :: "n"(n))
#define CP_WAITALL() asm volatile("cp.async.wait_all;")

// exp2 on packed half2
__device__ __forceinline__ uint32_t ex2h2(float t0, float t1) {
    uint32_t r, t = h2(t0, t1);
    asm("ex2.approx.f16x2 %0, %1;" : "=r"(r) : "r"(t));
    return r;
}

// ---------------------------------------------------------------------------
// Converters
// ---------------------------------------------------------------------------
__global__ void cvt_x(const float* __restrict__ x)
{
    size_t i = (size_t)blockIdx.x * 256 + threadIdx.x;
    float4 v = ((const float4*)x)[i];
    ((uint2*)g_xh)[i] = make_uint2(h2(v.x, v.y), h2(v.z, v.w));
}

__global__ void cvt_w(const float* __restrict__ W, int Ncols, int which)
{
    uint32_t* dst = which ? g_w2h : g_w1h;
    __shared__ float t[32][33];
    int n0 = blockIdx.x * 32, k0 = blockIdx.y * 32;
    int tx = threadIdx.x, ty = threadIdx.y;
#pragma unroll
    for (int r = ty; r < 32; r += 8)
        t[r][tx] = W[(size_t)(k0 + r) * Ncols + n0 + tx];
    __syncthreads();
#pragma unroll
    for (int r = ty; r < 32; r += 8)
        if (tx < 16)
            dst[(size_t)(n0 + r) * K2G + (k0 >> 1) + tx] =
                h2(t[2 * tx][r], t[2 * tx + 1][r]);
}

// ---------------------------------------------------------------------------
// fp16 GEMM, 4-stage cp.async pipeline + ldmatrix.
// BM=BN=128, BK=32, 256 thr (8 warps 2x4, warp tile 64x32).
// Stage (u32): A 128x20, B 128x20 -> 5120 u32/stage, 4 stages = 81920 B.
// mode 0: A=g_xh, B=g_w1h, epilogue q/k interleaved + V planar via smem
//         transpose.  mode 1: A=g_ctxh, B=g_w2h, fp32 C.
// ---------------------------------------------------------------------------
#define GEMM_SMEM_BYTES (4*5120*4)

__global__ __launch_bounds__(256, 2)
void mma_gemm(const float* __restrict__ bias, float* __restrict__ C,
              int N, int mode)
{
    extern __shared__ uint32_t gsm[];

    const uint32_t* Ah = mode ? g_ctxh : g_xh;
    const uint32_t* Bh = mode ? g_w2h : g_w1h;

    const int tid = threadIdx.x;
    const int lane = tid & 31;
    const int wid = tid >> 5;
    const int wm = (wid & 1) * 64;
    const int wn = (wid >> 1) * 32;
    const int rowBase = blockIdx.y * 128;
    const int colBase = blockIdx.x * 128;

    const int arow = ((lane >> 3) & 1) * 8 + (lane & 7);
    const int acol = ((lane >> 4) & 1) * 4;
    const int brow = ((lane >> 4) & 1) * 8 + (lane & 7);
    const int bcol = ((lane >> 3) & 1) * 4;

    // cp.async mapping: 512 16B-chunks per operand, 2 per thread each
    const int cr = tid >> 2;           // 0..63 (+64)
    const int co = (tid & 3) * 4;
    const uint32_t* Asrc0 = Ah + (size_t)(rowBase + cr) * K2G + co;
    const uint32_t* Asrc1 = Ah + (size_t)(rowBase + cr + 64) * K2G + co;
    const uint32_t* Bsrc0 = Bh + (size_t)(colBase + cr) * K2G + co;
    const uint32_t* Bsrc1 = Bh + (size_t)(colBase + cr + 64) * K2G + co;
    const uint32_t sbase = smem_u32(gsm);
    const uint32_t dA0 = sbase + (cr * 20 + co) * 4;
    const uint32_t dA1 = sbase + ((cr + 64) * 20 + co) * 4;
    const uint32_t dB0 = sbase + (2560 + cr * 20 + co) * 4;
    const uint32_t dB1 = sbase + (2560 + (cr + 64) * 20 + co) * 4;

    float acc[4][4][4];
#pragma unroll
    for (int i = 0; i < 4; i++)
#pragma unroll
        for (int j = 0; j < 4; j++)
#pragma unroll
            for (int r = 0; r < 4; r++) acc[i][j][r] = 0.f;

    const int KT = 32;
    auto prefetch = [&](int st, int kt) {
        if (kt < KT) {
            uint32_t so = st * 5120 * 4;
            CP16(dA0 + so, Asrc0 + kt * 16);
            CP16(dA1 + so, Asrc1 + kt * 16);
            CP16(dB0 + so, Bsrc0 + kt * 16);
            CP16(dB1 + so, Bsrc1 + kt * 16);
        }
        CP_COMMIT();
    };

    prefetch(0, 0); prefetch(1, 1); prefetch(2, 2);

    for (int kt = 0; kt < KT; kt++) {
        const int st = kt & 3;
        CP_WAIT(2);
        __syncthreads();
        prefetch((kt + 3) & 3, kt + 3);

        const uint32_t sa = sbase + st * 5120 * 4;
        const uint32_t sb = sa + 2560 * 4;
#pragma unroll
        for (int c = 0; c < 2; c++) {
            uint32_t af[4][4], bf[4][2];
#pragma unroll
            for (int mf = 0; mf < 4; mf++)
                LDSM4(af[mf][0], af[mf][1], af[mf][2], af[mf][3],
                      sa + ((wm + mf * 16 + arow) * 20 + c * 8 + acol) * 4);
#pragma unroll
            for (int np = 0; np < 2; np++)
                LDSM4(bf[2*np][0], bf[2*np][1], bf[2*np+1][0], bf[2*np+1][1],
                      sb + ((wn + np * 16 + brow) * 20 + c * 8 + bcol) * 4);
#pragma unroll
            for (int mf = 0; mf < 4; mf++)
#pragma unroll
                for (int nf = 0; nf < 4; nf++)
                    MMA_F16(acc[mf][nf], af[mf][0], af[mf][1], af[mf][2], af[mf][3],
                            bf[nf][0], bf[nf][1]);
        }
    }

    const int egr = lane >> 2;
    const int elc = lane & 3;

    if (mode == 0 && colBase >= 2048) {
        // V region: stage into smem [128 m][140 halves], write planar coalesced
        CP_WAITALL();
        __syncthreads();
        __half* smh = (__half*)gsm;
#pragma unroll
        for (int mf = 0; mf < 4; mf++)
#pragma unroll
            for (int nf = 0; nf < 4; nf++) {
                int nl = wn + nf * 8 + elc * 2;
                float bi0 = bias[colBase + nl], bi1 = bias[colBase + nl + 1];
#pragma unroll
                for (int half = 0; half < 2; half++) {
                    int ml = wm + mf * 16 + half * 8 + egr;
                    ((uint32_t*)smh)[ml * 70 + (nl >> 1)] =
                        h2(acc[mf][nf][half*2+0] + bi0,
                           acc[mf][nf][half*2+1] + bi1);
                }
            }
        __syncthreads();
        const int bb = rowBase >> 11, ssb = rowBase & (SEQ - 1);
        __half* vh = (__half*)g_vh;
#pragma unroll
        for (int it = 0; it < 8; it++) {
            int n = it * 16 + wid * 2 + (lane >> 4);
            int sc = (lane & 15) * 8;
            uint32_t w[4];
#pragma unroll
            for (int j = 0; j < 4; j++) {
                __half lo = smh[(sc + 2*j) * 140 + n];
                __half hi = smh[(sc + 2*j + 1) * 140 + n];
                w[j] = ((uint32_t)__half_as_ushort(hi) << 16) | __half_as_ushort(lo);
            }
            int n0 = colBase + n;
            int h = (n0 >> 6) & (NH - 1), d = n0 & 63;
            size_t off = ((size_t)(bb * NH + h) * DK + d) * SEQ + ssb + sc;
            *(uint4*)(vh + off) = make_uint4(w[0], w[1], w[2], w[3]);
        }
        return;
    }

#pragma unroll
    for (int mf = 0; mf < 4; mf++) {
#pragma unroll
        for (int nf = 0; nf < 4; nf++) {
            int m0 = rowBase + wm + mf * 16 + egr;
            int n0 = colBase + wn + nf * 8 + elc * 2;
            float bi0 = bias[n0], bi1 = bias[n0 + 1];
            if (mode == 0) {
                int qkv = n0 >> 10;
                int h = (n0 >> 6) & (NH - 1);
                int d2 = (n0 & 63) >> 1;
                float sc = (qkv == 0) ? 0.125f : 1.f;
                uint32_t* dst = (qkv == 0) ? g_qh : g_kh;
#pragma unroll
                for (int half = 0; half < 2; half++) {
                    int m = m0 + half * 8;
                    int bb = m >> 11, ss = m & (SEQ - 1);
                    dst[(((size_t)bb * NH + h) * SEQ + ss) * 32 + d2] =
                        h2((acc[mf][nf][half*2+0] + bi0) * sc,
                           (acc[mf][nf][half*2+1] + bi1) * sc);
                }
            } else {
#pragma unroll
                for (int half = 0; half < 2; half++) {
                    int m = m0 + half * 8;
                    float* p = C + (size_t)m * N + n0;
                    p[0] = acc[mf][nf][half*2+0] + bi0;
                    p[1] = acc[mf][nf][half*2+1] + bi1;
                }
            }
        }
    }
}

// ---------------------------------------------------------------------------
// fp16 flash attention: 3-stage cp.async pipeline, ldmatrix, planar V,
// register softmax with ex2.approx.f16x2 producing fp16 P directly.
// 128 thr = 4 warps; warp = 32 q x 64; BQ=128, BK=64, 32 tiles.
// smem u32: Qs[128][36] | Ks[3][64][36] | Vs[3][64][36] = 73728 B
// ---------------------------------------------------------------------------
#define ATTN_SMEM_BYTES ((4608 + 3*2304 + 3*2304) * 4)

__global__ __launch_bounds__(128, 2)
void attn_mma()
{
    extern __shared__ uint32_t sm[];
    const uint32_t qsb = smem_u32(sm);
    const uint32_t ksb = qsb + 4608 * 4;
    const uint32_t vsb = ksb + 3 * 2304 * 4;

    const int tid = threadIdx.x;
    const int lane = tid & 31;
    const int wid = tid >> 5;
    const int gr = lane >> 2;
    const int lc = lane & 3;
    const int q0 = blockIdx.x * 128;
    const int bh = blockIdx.y;
    const int wrow = wid * 32;

    const int arow = ((lane >> 3) & 1) * 8 + (lane & 7);
    const int acol = ((lane >> 4) & 1) * 4;
    const int brow = ((lane >> 4) & 1) * 8 + (lane & 7);
    const int bcol = ((lane >> 3) & 1) * 4;

    const uint32_t* Kg = g_kh + (size_t)bh * SEQ * 32;
    const uint32_t* Vg = g_vh + (size_t)bh * DK * (SEQ / 2);

    // Q tile once
    {
        const uint4* Qg4 = (const uint4*)(g_qh + ((size_t)bh * SEQ + q0) * 32);
#pragma unroll
        for (int it = 0; it < 8; it++) {
            int i = tid + it * 128;
            int r = i >> 3, c = i & 7;
            *(uint4*)&sm[r * 36 + c * 4] = Qg4[r * 8 + c];
        }
    }

    const int NT = SEQ / 64;
    auto prefetch = [&](int st, int kt) {
        if (kt < NT) {
#pragma unroll
            for (int i = 0; i < 4; i++) {
                int c = tid + i * 128;
                int row = c >> 3, off = (c & 7) * 4;
                CP16(ksb + (st * 2304 + row * 36 + off) * 4,
                     Kg + (size_t)(kt * 64 + row) * 32 + off);
                CP16(vsb + (st * 2304 + row * 36 + off) * 4,
                     Vg + (size_t)row * (SEQ / 2) + kt * 32 + off);
            }
        }
        CP_COMMIT();
    };

    float o[2][8][4];
#pragma unroll
    for (int mf = 0; mf < 2; mf++)
#pragma unroll
        for (int nf = 0; nf < 8; nf++)
#pragma unroll
            for (int r = 0; r < 4; r++) o[mf][nf][r] = 0.f;
    float mrow[2][2] = { {-1e30f, -1e30f}, {-1e30f, -1e30f} };
    float lrow[2][2] = { {0.f, 0.f}, {0.f, 0.f} };

    prefetch(0, 0); prefetch(1, 1);

    for (int kt = 0; kt < NT; kt++) {
        const int st = kt - (kt / 3) * 3;     // kt % 3
        CP_WAIT(1);
        __syncthreads();
        {
            int nx = kt + 2;
            int sx = nx - (nx / 3) * 3;
            prefetch(sx, nx);
        }

        // S = Q @ K^T
        float ps[2][8][4];
#pragma unroll
        for (int mf = 0; mf < 2; mf++)
#pragma unroll
            for (int nf = 0; nf < 8; nf++)
#pragma unroll
                for (int r = 0; r < 4; r++) ps[mf][nf][r] = 0.f;

#pragma unroll
        for (int ch = 0; ch < 4; ch++) {
            uint32_t a[2][4], bK[8][2];
#pragma unroll
            for (int mf = 0; mf < 2; mf++)
                LDSM4(a[mf][0], a[mf][1], a[mf][2], a[mf][3],
                      qsb + ((wrow + mf * 16 + arow) * 36 + ch * 8 + acol) * 4);
#pragma unroll
            for (int np = 0; np < 4; np++)
                LDSM4(bK[2*np][0], bK[2*np][1], bK[2*np+1][0], bK[2*np+1][1],
                      ksb + (st * 2304 + (np * 16 + brow) * 36 + ch * 8 + bcol) * 4);
#pragma unroll
            for (int nf = 0; nf < 8; nf++) {
                MMA_F16(ps[0][nf], a[0][0], a[0][1], a[0][2], a[0][3],
                        bK[nf][0], bK[nf][1]);
                MMA_F16(ps[1][nf], a[1][0], a[1][1], a[1][2], a[1][3],
                        bK[nf][0], bK[nf][1]);
            }
        }

        // Online softmax -> fp16 P via ex2.f16x2
        uint32_t pp[2][8][2];
#pragma unroll
        for (int mf = 0; mf < 2; mf++) {
#pragma unroll
            for (int h = 0; h < 2; h++) {
                float mx = -1e30f;
#pragma unroll
                for (int nf = 0; nf < 8; nf++)
                    mx = fmaxf(mx, fmaxf(ps[mf][nf][2*h], ps[mf][nf][2*h+1]));
                mx = fmaxf(mx, __shfl_xor_sync(0xffffffffu, mx, 1));
                mx = fmaxf(mx, __shfl_xor_sync(0xffffffffu, mx, 2));
                float mnew = fmaxf(mrow[mf][h], mx);
                float corr = __expf(mrow[mf][h] - mnew);
                float mL = mnew * LOG2E;
                float sum = 0.f;
#pragma unroll
                for (int nf = 0; nf < 8; nf++) {
                    float t0 = fmaf(ps[mf][nf][2*h],   LOG2E, -mL);
                    float t1 = fmaf(ps[mf][nf][2*h+1], LOG2E, -mL);
                    uint32_t ph = ex2h2(t0, t1);
                    pp[mf][nf][h] = ph;
                    float2 f = __half22float2(*(__half2*)&ph);
                    sum += f.x + f.y;
                }
                sum += __shfl_xor_sync(0xffffffffu, sum, 1);
                sum += __shfl_xor_sync(0xffffffffu, sum, 2);
                lrow[mf][h] = lrow[mf][h] * corr + sum;
                mrow[mf][h] = mnew;
#pragma unroll
                for (int nf = 0; nf < 8; nf++) {
                    o[mf][nf][2*h]   *= corr;
                    o[mf][nf][2*h+1] *= corr;
                }
            }
        }

        // O += P @ V
#pragma unroll
        for (int kf = 0; kf < 4; kf++) {
            uint32_t bV[8][2];
#pragma unroll
            for (int np = 0; np < 4; np++)
                LDSM4(bV[2*np][0], bV[2*np][1], bV[2*np+1][0], bV[2*np+1][1],
                      vsb + (st * 2304 + (np * 16 + brow) * 36 + kf * 8 + bcol) * 4);
#pragma unroll
            for (int nf = 0; nf < 8; nf++) {
                MMA_F16(o[0][nf], pp[0][2*kf][0], pp[0][2*kf][1],
                        pp[0][2*kf+1][0], pp[0][2*kf+1][1], bV[nf][0], bV[nf][1]);
                MMA_F16(o[1][nf], pp[1][2*kf][0], pp[1][2*kf][1],
                        pp[1][2*kf+1][0], pp[1][2*kf+1][1], bV[nf][0], bV[nf][1]);
            }
        }
    }

    // epilogue -> g_ctxh fp16-packed [m][512]
    const int bb = bh >> 4;
    const int h_head = bh & (NH - 1);
#pragma unroll
    for (int mf = 0; mf < 2; mf++) {
#pragma unroll
        for (int half = 0; half < 2; half++) {
            float inv = 1.f / lrow[mf][half];
            int qrow = q0 + wrow + mf * 16 + half * 8 + gr;
            uint32_t* base = g_ctxh + ((size_t)bb * SEQ + qrow) * K2G
                           + h_head * 32 + lc;
#pragma unroll
            for (int nf = 0; nf < 8; nf++)
                base[nf * 4] = h2(o[mf][nf][2*half] * inv,
                                  o[mf][nf][2*half+1] * inv);
        }
    }
}

// ---------------------------------------------------------------------------
extern "C" void kernel_launch(void* const* d_in, const int* in_sizes, int n_in,
                              void* d_out, int out_size)
{
    const float* x  = (const float*)d_in[0];
    const float* W1 = (const float*)d_in[1];
    const float* b1 = (const float*)d_in[2];
    const float* W2 = (const float*)d_in[3];
    const float* b2 = (const float*)d_in[4];
    float* out = (float*)d_out;

    // 0) converters
    cvt_x<<<MROWS * HID / 4 / 256, 256>>>(x);
    cvt_w<<<dim3(QKV_N / 32, HID / 32), dim3(32, 8)>>>(W1, QKV_N, 0);
    cvt_w<<<dim3(HID / 32, HID / 32), dim3(32, 8)>>>(W2, HID, 1);

    cudaFuncSetAttribute(mma_gemm,
                         cudaFuncAttributeMaxDynamicSharedMemorySize,
                         GEMM_SMEM_BYTES);
    cudaFuncSetAttribute(attn_mma,
                         cudaFuncAttributeMaxDynamicSharedMemorySize,
                         ATTN_SMEM_BYTES);

    // 1) QKV projection -> q/k interleaved + V planar, q pre-scaled
    mma_gemm<<<dim3(QKV_N / 128, MROWS / 128), 256, GEMM_SMEM_BYTES>>>(
        b1, nullptr, QKV_N, 0);

    // 2) flash attention -> g_ctxh
    attn_mma<<<dim3(SEQ / 128, BATCH * NH), 128, ATTN_SMEM_BYTES>>>();

    // 3) output projection -> fp32 out
    mma_gemm<<<dim3(HID / 128, MROWS / 128), 256, GEMM_SMEM_BYTES>>>(
        b2, out, HID, 1);
}